// round 13
// baseline (speedup 1.0000x reference)
#include <cuda_runtime.h>
#include <cuda_bf16.h>
#include <cuda_fp16.h>
#include <math.h>
#include <cstdint>
#include <cstddef>

#define T_SEQ 2048
#define HID_DIM 2048
#define NH 16
#define NKV 4
#define HD 128
#define QKV_N ((NH + 2 * NKV) * HD)   // 3072
#define CTX_N (NH * HD)               // 2048
// 1/sqrt(128) * log2(e): scores computed in log2 domain, softmax via exp2
#define SCALEL2 0.12753139578983588f

// ---------------- scratch (no cudaMalloc allowed) ----------------
__device__ float g_qkv[T_SEQ * QKV_N];
__device__ __half g_hid_h[T_SEQ * HID_DIM];
__device__ __half g_wqkvT_h[QKV_N * HID_DIM];
__device__ __half g_wqkvT_l[QKV_N * HID_DIM];
__device__ __half g_woT_h[HID_DIM * CTX_N];
__device__ __half g_woT_l[HID_DIM * CTX_N];
__device__ __half g_ctx_h[T_SEQ * CTX_N];
__device__ __nv_bfloat16 g_qh[T_SEQ * NH * HD];
__device__ __nv_bfloat16 g_ql[T_SEQ * NH * HD];
__device__ __nv_bfloat16 g_kh[T_SEQ * NKV * HD];
__device__ __nv_bfloat16 g_kl[T_SEQ * NKV * HD];
__device__ __nv_bfloat16 g_vh[T_SEQ * NKV * HD];
__device__ __nv_bfloat16 g_vl[T_SEQ * NKV * HD];

// ---------------- tiny helpers ----------------
__device__ __forceinline__ uint32_t packbf(float lo, float hi) {
    uint32_t r;
    asm("cvt.rn.bf16x2.f32 %0, %1, %2;" : "=r"(r) : "f"(hi), "f"(lo));
    return r;
}
__device__ __forceinline__ float bfres(float x) {
    return x - __bfloat162float(__float2bfloat16(x));
}

#define MMA4BF(d, a, b0_, b1_)                                                \
    asm volatile(                                                             \
        "mma.sync.aligned.m16n8k16.row.col.f32.bf16.bf16.f32 "                \
        "{%0,%1,%2,%3}, {%4,%5,%6,%7}, {%8,%9}, {%0,%1,%2,%3};\n"             \
        : "+f"((d)[0]), "+f"((d)[1]), "+f"((d)[2]), "+f"((d)[3])              \
        : "r"((a)[0]), "r"((a)[1]), "r"((a)[2]), "r"((a)[3]),                 \
          "r"(b0_), "r"(b1_))

#define MMA4H(d, a, b0_, b1_)                                                 \
    asm volatile(                                                             \
        "mma.sync.aligned.m16n8k16.row.col.f32.f16.f16.f32 "                  \
        "{%0,%1,%2,%3}, {%4,%5,%6,%7}, {%8,%9}, {%0,%1,%2,%3};\n"             \
        : "+f"((d)[0]), "+f"((d)[1]), "+f"((d)[2]), "+f"((d)[3])              \
        : "r"((a)[0]), "r"((a)[1]), "r"((a)[2]), "r"((a)[3]),                 \
          "r"(b0_), "r"(b1_))

#define LDSM_X4(r0, r1, r2, r3, a)                                            \
    asm volatile("ldmatrix.sync.aligned.m8n8.x4.shared.b16 {%0,%1,%2,%3}, [%4];" \
                 : "=r"(r0), "=r"(r1), "=r"(r2), "=r"(r3) : "r"(a))

#define LDSM_X4_T(r0, r1, r2, r3, a)                                          \
    asm volatile("ldmatrix.sync.aligned.m8n8.x4.trans.shared.b16 {%0,%1,%2,%3}, [%4];" \
                 : "=r"(r0), "=r"(r1), "=r"(r2), "=r"(r3) : "r"(a))

#define CP16(dst, src)                                                        \
    asm volatile("cp.async.cg.shared.global [%0], [%1], 16;\n"                \
                 :: "r"(dst), "l"(src))
#define CP_COMMIT() asm volatile("cp.async.commit_group;\n" ::: "memory")
#define CP_WAIT1()  asm volatile("cp.async.wait_group 1;\n" ::: "memory")

// ---------------------------------------------------------------------------
// fp32 -> fp16 convert.
// ---------------------------------------------------------------------------
__global__ void conv16_kernel(const float* __restrict__ X, __half* __restrict__ Y)
{
    const size_t i = ((size_t)blockIdx.x * blockDim.x + threadIdx.x) * 4;
    float4 v = *(const float4*)&X[i];
    *(__half2*)&Y[i]     = __floats2half2_rn(v.x, v.y);
    *(__half2*)&Y[i + 2] = __floats2half2_rn(v.z, v.w);
}

// ---------------------------------------------------------------------------
// Split + transpose: W[Kd][N] fp32 -> Wt hi/lo fp16 [N][Kd].
// ---------------------------------------------------------------------------
__global__ void split_T16_kernel(const float* __restrict__ W,
                                 __half* __restrict__ hi, __half* __restrict__ lo,
                                 int Kd, int N)
{
    __shared__ float tile[32][33];
    const int n0 = blockIdx.x * 32;
    const int k0 = blockIdx.y * 32;
    const int tx = threadIdx.x, ty = threadIdx.y;
#pragma unroll
    for (int i = 0; i < 32; i += 8)
        tile[ty + i][tx] = W[(size_t)(k0 + ty + i) * N + n0 + tx];
    __syncthreads();
#pragma unroll
    for (int i = 0; i < 32; i += 8) {
        const float v = tile[tx][ty + i];
        const __half h = __float2half_rn(v);
        const size_t o = (size_t)(n0 + ty + i) * Kd + k0 + tx;
        hi[o] = h;
        lo[o] = __float2half_rn(v - __half2float(h));
    }
}

// ---------------------------------------------------------------------------
// fp16x2 GEMM (unchanged from round 12).
// ---------------------------------------------------------------------------
#define TCAB 8192
#define SLOTB (3 * TCAB)
#define GEMM_SMEM (3 * SLOTB)

__global__ __launch_bounds__(128, 2) void gemm_f16x2_kernel(
    const __half* __restrict__ Ah,
    const __half* __restrict__ Bh, const __half* __restrict__ Bl,
    float* __restrict__ C, int M, int N, int Kd)
{
    extern __shared__ __half gsm[];
    const uint32_t smem0 = (uint32_t)__cvta_generic_to_shared(gsm);

    const int tid  = threadIdx.x;
    const int lane = tid & 31;
    const int wid  = tid >> 5;
    const int g    = lane >> 2;
    const int cq   = lane & 3;
    const int wm   = wid & 1;
    const int wn   = wid >> 1;
    const int row0 = blockIdx.y * 128;
    const int col0 = blockIdx.x * 128;

    const int lm  = lane >> 3;
    const int row_local = ((lm & 1) << 3) + (lane & 7);
    const int chi = lm >> 1;
    const int xorv = (row_local >> 1) & 3;
    const int lo0 = row_local * 64 + (((0 | chi) ^ xorv) << 4);
    const int lo1 = row_local * 64 + (((2 | chi) ^ xorv) << 4);

    uint32_t dsw[4];
    int goff[4];
#pragma unroll
    for (int i = 0; i < 4; i++) {
        const int c = i * 128 + tid;
        const int r = c >> 2, cc = c & 3;
        dsw[i] = r * 64 + ((cc ^ ((r >> 1) & 3)) << 4);
        goff[i] = r * Kd + cc * 8;
    }

    const __half* pAh = Ah + (size_t)row0 * Kd;
    const __half* pBh = Bh + (size_t)col0 * Kd;
    const __half* pBl = Bl + (size_t)col0 * Kd;

    const int nK = Kd >> 5;

    float acc[4][8][4];
#pragma unroll
    for (int i = 0; i < 4; i++)
#pragma unroll
        for (int j = 0; j < 8; j++)
#pragma unroll
            for (int e = 0; e < 4; e++) acc[i][j][e] = 0.0f;

#pragma unroll
    for (int pf = 0; pf < 2; pf++) {
        const int k0 = pf * 32;
        const uint32_t sb = smem0 + pf * SLOTB;
#pragma unroll
        for (int i = 0; i < 4; i++) {
            CP16(sb + dsw[i],            pAh + goff[i] + k0);
            CP16(sb + TCAB + dsw[i],     pBh + goff[i] + k0);
            CP16(sb + 2 * TCAB + dsw[i], pBl + goff[i] + k0);
        }
        CP_COMMIT();
    }

    int scur = 0, spre = 2;
    for (int kt = 0; kt < nK; kt++) {
        CP_WAIT1();
        __syncthreads();

        if (kt + 2 < nK) {
            const int k0 = (kt + 2) * 32;
            const uint32_t db = smem0 + spre * SLOTB;
#pragma unroll
            for (int i = 0; i < 4; i++) {
                CP16(db + dsw[i],            pAh + goff[i] + k0);
                CP16(db + TCAB + dsw[i],     pBh + goff[i] + k0);
                CP16(db + 2 * TCAB + dsw[i], pBl + goff[i] + k0);
            }
        }
        CP_COMMIT();

        const uint32_t sb  = smem0 + scur * SLOTB;
        const uint32_t sAh = sb;
        const uint32_t sBh = sb + TCAB;
        const uint32_t sBl = sb + 2 * TCAB;

#pragma unroll
        for (int ks2 = 0; ks2 < 2; ks2++) {
            const int lo = ks2 ? lo1 : lo0;
            uint32_t ah[4][4], bh[8][2], bl[8][2];
#pragma unroll
            for (int mt = 0; mt < 4; mt++) {
                const int off = (wm * 64 + mt * 16) * 64 + lo;
                LDSM_X4(ah[mt][0], ah[mt][1], ah[mt][2], ah[mt][3], sAh + off);
            }
#pragma unroll
            for (int np = 0; np < 4; np++) {
                const int off = (wn * 64 + np * 16) * 64 + lo;
                uint32_t t0, t1, t2, t3;
                LDSM_X4(t0, t1, t2, t3, sBh + off);
                bh[2 * np][0] = t0; bh[2 * np + 1][0] = t1;
                bh[2 * np][1] = t2; bh[2 * np + 1][1] = t3;
                LDSM_X4(t0, t1, t2, t3, sBl + off);
                bl[2 * np][0] = t0; bl[2 * np + 1][0] = t1;
                bl[2 * np][1] = t2; bl[2 * np + 1][1] = t3;
            }
#pragma unroll
            for (int mt = 0; mt < 4; mt++)
#pragma unroll
                for (int nt = 0; nt < 8; nt++) MMA4H(acc[mt][nt], ah[mt], bh[nt][0], bh[nt][1]);
#pragma unroll
            for (int mt = 0; mt < 4; mt++)
#pragma unroll
                for (int nt = 0; nt < 8; nt++) MMA4H(acc[mt][nt], ah[mt], bl[nt][0], bl[nt][1]);
        }

        scur = (scur == 2) ? 0 : scur + 1;
        spre = (spre == 2) ? 0 : spre + 1;
    }

#pragma unroll
    for (int mt = 0; mt < 4; mt++) {
        const int r0 = row0 + wm * 64 + mt * 16 + g;
#pragma unroll
        for (int nt = 0; nt < 8; nt++) {
            const int cb = col0 + wn * 64 + nt * 8 + 2 * cq;
            *(float2*)&C[(size_t)r0 * N + cb]       = make_float2(acc[mt][nt][0], acc[mt][nt][1]);
            *(float2*)&C[(size_t)(r0 + 8) * N + cb] = make_float2(acc[mt][nt][2], acc[mt][nt][3]);
        }
    }
}

// ---------------------------------------------------------------------------
// RoPE + scale(log2e folded) + hi/lo bf16 split.
// ---------------------------------------------------------------------------
__global__ void rope_split_kernel(const float* __restrict__ qkv,
                                  const int* __restrict__ pos,
                                  __nv_bfloat16* __restrict__ qh, __nv_bfloat16* __restrict__ ql,
                                  __nv_bfloat16* __restrict__ kh, __nv_bfloat16* __restrict__ kl,
                                  __nv_bfloat16* __restrict__ vh, __nv_bfloat16* __restrict__ vl)
{
    const int t = blockIdx.x;
    const int tid = threadIdx.x;
    const float p = (float)pos[t];
    const float* base = qkv + (size_t)t * QKV_N;

#pragma unroll
    for (int it = 0; it < 8; it++) {
        const int item = it * 128 + tid;
        const int head = item >> 6, j = item & 63;
        const float invf = powf(10000.0f, -((float)j) * (1.0f / 64.0f));
        float s, c; sincosf(p * invf, &s, &c);
        const float x1 = base[head * HD + j];
        const float x2 = base[head * HD + j + 64];
        const float y1 = (x1 * c - x2 * s) * SCALEL2;
        const float y2 = (x2 * c + x1 * s) * SCALEL2;
        const size_t o = (size_t)t * (NH * HD) + head * HD + j;
        __nv_bfloat16 h1 = __float2bfloat16(y1), h2 = __float2bfloat16(y2);
        qh[o] = h1;      ql[o]      = __float2bfloat16(y1 - __bfloat162float(h1));
        qh[o + 64] = h2; ql[o + 64] = __float2bfloat16(y2 - __bfloat162float(h2));
    }
#pragma unroll
    for (int it = 0; it < 2; it++) {
        const int item = it * 128 + tid;
        const int head = item >> 6, j = item & 63;
        const float invf = powf(10000.0f, -((float)j) * (1.0f / 64.0f));
        float s, c; sincosf(p * invf, &s, &c);
        const float x1 = base[NH * HD + head * HD + j];
        const float x2 = base[NH * HD + head * HD + j + 64];
        const float y1 = x1 * c - x2 * s;
        const float y2 = x2 * c + x1 * s;
        const size_t o = (size_t)t * (NKV * HD) + head * HD + j;
        __nv_bfloat16 h1 = __float2bfloat16(y1), h2 = __float2bfloat16(y2);
        kh[o] = h1;      kl[o]      = __float2bfloat16(y1 - __bfloat162float(h1));
        kh[o + 64] = h2; kl[o + 64] = __float2bfloat16(y2 - __bfloat162float(h2));
    }
#pragma unroll
    for (int it = 0; it < 4; it++) {
        const int idx = it * 128 + tid;
        const float x = base[(NH + NKV) * HD + idx];
        const size_t o = (size_t)t * (NKV * HD) + idx;
        __nv_bfloat16 h = __float2bfloat16(x);
        vh[o] = h; vl[o] = __float2bfloat16(x - __bfloat162float(h));
    }
}

// ---------------------------------------------------------------------------
// Flash attention v4: r9 shape (BQ=BK=64, 128 threads, 69632B smem,
// 3 CTAs/SM) + phase-split cp.async pipeline: K(kb+1) loads during
// softmax+PV(kb); V(kb+1) loads during S(kb+1). exp2-domain softmax.
// ---------------------------------------------------------------------------
#define PITCH 136
#define PITCHB (PITCH * 2)
#define KVARR (64 * PITCH)            // elems per array
#define AT_SMEM (4 * 64 * PITCH * 2)  // 69632

__device__ __forceinline__ void attn_load2(
    uint32_t s_hi, uint32_t s_lo,
    const __nv_bfloat16* __restrict__ hi, const __nv_bfloat16* __restrict__ lo,
    int r0, int kvh, int tid)
{
#pragma unroll
    for (int i = 0; i < 8; i++) {
        const int idx = i * 128 + tid;      // 1024 chunks per array
        const int row = idx >> 4;
        const int cb  = (idx & 15) * 16;    // byte offset in row
        const uint32_t d = row * PITCHB + cb;
        const size_t gs = (size_t)(r0 + row) * (NKV * HD) + kvh * HD + (cb >> 1);
        CP16(s_hi + d, hi + gs);
        CP16(s_lo + d, lo + gs);
    }
}

__global__ __launch_bounds__(128) void attn_mma_kernel(
    const __nv_bfloat16* __restrict__ qh, const __nv_bfloat16* __restrict__ ql,
    const __nv_bfloat16* __restrict__ kh, const __nv_bfloat16* __restrict__ kl,
    const __nv_bfloat16* __restrict__ vh, const __nv_bfloat16* __restrict__ vl,
    __half* __restrict__ ctxh)
{
    extern __shared__ __nv_bfloat16 sm[];
    __nv_bfloat16* Kh = sm;
    __nv_bfloat16* Kl = sm + KVARR;

    const int tid  = threadIdx.x;
    const int lane = tid & 31;
    const int w    = tid >> 5;
    const int gr   = lane >> 2;
    const int tq   = lane & 3;
    const int qb   = (int)gridDim.x - 1 - (int)blockIdx.x;
    const int h    = blockIdx.y;
    const int kvh  = h >> 2;
    const int q0   = qb * 64;

    const int lm = lane >> 3;
    const int laneoff = (((lm & 1) << 3) + (lane & 7)) * PITCHB + ((lm >> 1) << 3) * 2;

    const uint32_t s0u = (uint32_t)__cvta_generic_to_shared(sm);
    const uint32_t sKh = s0u;
    const uint32_t sKl = s0u + KVARR * 2;
    const uint32_t sVh = s0u + 2 * KVARR * 2;
    const uint32_t sVl = s0u + 3 * KVARR * 2;

    // ---- stage Q into K area, extract fragments ----
#pragma unroll
    for (int it = 0; it < 8; it++) {
        const int idx = it * 128 + tid;
        const int row = idx >> 4;
        const int cc  = (idx & 15) * 8;
        const size_t gs = (size_t)(q0 + row) * (NH * HD) + h * HD + cc;
        *(uint4*)&Kh[row * PITCH + cc] = *(const uint4*)&qh[gs];
        *(uint4*)&Kl[row * PITCH + cc] = *(const uint4*)&ql[gs];
    }
    __syncthreads();

    uint32_t qfh[8][4], qfl[8][4];
#pragma unroll
    for (int ks = 0; ks < 8; ks++) {
        LDSM_X4(qfh[ks][0], qfh[ks][1], qfh[ks][2], qfh[ks][3],
                sKh + (16 * w) * PITCHB + (16 * ks) * 2 + laneoff);
        LDSM_X4(qfl[ks][0], qfl[ks][1], qfl[ks][2], qfl[ks][3],
                sKl + (16 * w) * PITCHB + (16 * ks) * 2 + laneoff);
    }
    __syncthreads();   // Q reads done; K area free

    // ---- prologue: issue K(0) then V(0), separate groups ----
    attn_load2(sKh, sKl, kh, kl, 0, kvh, tid);
    CP_COMMIT();                                   // group: K(0)
    attn_load2(sVh, sVl, vh, vl, 0, kvh, tid);
    CP_COMMIT();                                   // group: V(0)

    float o[16][4];
#pragma unroll
    for (int i = 0; i < 16; i++)
#pragma unroll
        for (int e = 0; e < 4; e++) o[i][e] = 0.0f;
    float mrun0 = -1e30f, mrun1 = -1e30f, lrun0 = 0.0f, lrun1 = 0.0f;

    for (int kb = 0; kb <= qb; kb++) {
        const int k0 = kb * 64;

        // ---- wait K(kb) (all groups except most recent [V(kb) or K(kb+1)]) ----
        CP_WAIT1();
        __syncthreads();

        // ---- S = Q @ K^T (bf16x3) ----
        float s[8][4];
#pragma unroll
        for (int i = 0; i < 8; i++)
#pragma unroll
            for (int e = 0; e < 4; e++) s[i][e] = 0.0f;

#pragma unroll
        for (int nt2 = 0; nt2 < 4; nt2++) {
#pragma unroll
            for (int ks = 0; ks < 8; ks++) {
                const int toff = (16 * nt2) * PITCHB + (16 * ks) * 2 + laneoff;
                uint32_t kh0, kh1, kh2, kh3, kl0, kl1, kl2, kl3;
                LDSM_X4(kh0, kh1, kh2, kh3, sKh + toff);
                LDSM_X4(kl0, kl1, kl2, kl3, sKl + toff);
                MMA4BF(s[2 * nt2],     qfh[ks], kh0, kh2);
                MMA4BF(s[2 * nt2],     qfh[ks], kl0, kl2);
                MMA4BF(s[2 * nt2],     qfl[ks], kh0, kh2);
                MMA4BF(s[2 * nt2 + 1], qfh[ks], kh1, kh3);
                MMA4BF(s[2 * nt2 + 1], qfh[ks], kl1, kl3);
                MMA4BF(s[2 * nt2 + 1], qfl[ks], kh1, kh3);
            }
        }

        // ---- K buffer free: issue K(kb+1) (overlaps softmax + PV) ----
        __syncthreads();
        if (kb + 1 <= qb)
            attn_load2(sKh, sKl, kh, kl, k0 + 64, kvh, tid);
        CP_COMMIT();                               // group: K(kb+1) (maybe empty)

        // ---- causal mask (diagonal block only) ----
        if (kb == qb) {
            const int lr0 = 16 * w + gr;
#pragma unroll
            for (int nt = 0; nt < 8; nt++) {
                const int c0 = 8 * nt + 2 * tq;
                if (c0     > lr0)     s[nt][0] = -1e30f;
                if (c0 + 1 > lr0)     s[nt][1] = -1e30f;
                if (c0     > lr0 + 8) s[nt][2] = -1e30f;
                if (c0 + 1 > lr0 + 8) s[nt][3] = -1e30f;
            }
        }

        // ---- online softmax in exp2 domain ----
        float m0l = -1e30f, m1l = -1e30f;
#pragma unroll
        for (int nt = 0; nt < 8; nt++) {
            m0l = fmaxf(m0l, fmaxf(s[nt][0], s[nt][1]));
            m1l = fmaxf(m1l, fmaxf(s[nt][2], s[nt][3]));
        }
        m0l = fmaxf(m0l, __shfl_xor_sync(0xffffffffu, m0l, 1));
        m0l = fmaxf(m0l, __shfl_xor_sync(0xffffffffu, m0l, 2));
        m1l = fmaxf(m1l, __shfl_xor_sync(0xffffffffu, m1l, 1));
        m1l = fmaxf(m1l, __shfl_xor_sync(0xffffffffu, m1l, 2));
        const float mn0 = fmaxf(mrun0, m0l);
        const float mn1 = fmaxf(mrun1, m1l);
        const float corr0 = exp2f(mrun0 - mn0);
        const float corr1 = exp2f(mrun1 - mn1);
        mrun0 = mn0; mrun1 = mn1;
        float sum0 = 0.0f, sum1 = 0.0f;
#pragma unroll
        for (int nt = 0; nt < 8; nt++) {
            s[nt][0] = exp2f(s[nt][0] - mn0);
            s[nt][1] = exp2f(s[nt][1] - mn0);
            s[nt][2] = exp2f(s[nt][2] - mn1);
            s[nt][3] = exp2f(s[nt][3] - mn1);
            sum0 += s[nt][0] + s[nt][1];
            sum1 += s[nt][2] + s[nt][3];
        }
        sum0 += __shfl_xor_sync(0xffffffffu, sum0, 1);
        sum0 += __shfl_xor_sync(0xffffffffu, sum0, 2);
        sum1 += __shfl_xor_sync(0xffffffffu, sum1, 1);
        sum1 += __shfl_xor_sync(0xffffffffu, sum1, 2);
        lrun0 = lrun0 * corr0 + sum0;
        lrun1 = lrun1 * corr1 + sum1;

#pragma unroll
        for (int nt = 0; nt < 16; nt++) {
            o[nt][0] *= corr0; o[nt][1] *= corr0;
            o[nt][2] *= corr1; o[nt][3] *= corr1;
        }

        // ---- wait V(kb), then O += P @ V (bf16x3) ----
        CP_WAIT1();       // all groups except most recent [K(kb+1)] done
        __syncthreads();

#pragma unroll
        for (int kvs = 0; kvs < 4; kvs++) {
            uint32_t ph[4], pl[4];
            ph[0] = packbf(s[2 * kvs][0], s[2 * kvs][1]);
            ph[1] = packbf(s[2 * kvs][2], s[2 * kvs][3]);
            ph[2] = packbf(s[2 * kvs + 1][0], s[2 * kvs + 1][1]);
            ph[3] = packbf(s[2 * kvs + 1][2], s[2 * kvs + 1][3]);
            pl[0] = packbf(bfres(s[2 * kvs][0]), bfres(s[2 * kvs][1]));
            pl[1] = packbf(bfres(s[2 * kvs][2]), bfres(s[2 * kvs][3]));
            pl[2] = packbf(bfres(s[2 * kvs + 1][0]), bfres(s[2 * kvs + 1][1]));
            pl[3] = packbf(bfres(s[2 * kvs + 1][2]), bfres(s[2 * kvs + 1][3]));
#pragma unroll
            for (int dn2 = 0; dn2 < 8; dn2++) {
                const int toff = (16 * kvs) * PITCHB + (16 * dn2) * 2 + laneoff;
                uint32_t vh0, vh1, vh2, vh3, vl0, vl1, vl2, vl3;
                LDSM_X4_T(vh0, vh1, vh2, vh3, sVh + toff);
                LDSM_X4_T(vl0, vl1, vl2, vl3, sVl + toff);
                MMA4BF(o[2 * dn2],     ph, vh0, vh1);
                MMA4BF(o[2 * dn2],     pl, vh0, vh1);
                MMA4BF(o[2 * dn2],     ph, vl0, vl1);
                MMA4BF(o[2 * dn2 + 1], ph, vh2, vh3);
                MMA4BF(o[2 * dn2 + 1], pl, vh2, vh3);
                MMA4BF(o[2 * dn2 + 1], ph, vl2, vl3);
            }
        }

        // ---- V buffer free: issue V(kb+1) (overlaps next S) ----
        __syncthreads();
        if (kb + 1 <= qb)
            attn_load2(sVh, sVl, vh, vl, k0 + 64, kvh, tid);
        CP_COMMIT();                               // group: V(kb+1) (maybe empty)
    }

    // ---- epilogue: normalize, emit fp16 ctx ----
    const float inv0 = 1.0f / lrun0;
    const float inv1 = 1.0f / lrun1;
    const int row0 = q0 + 16 * w + gr;
    const int row1 = row0 + 8;
#pragma unroll
    for (int nt = 0; nt < 16; nt++) {
        const int col = h * HD + 8 * nt + 2 * tq;
        *(__half2*)&ctxh[(size_t)row0 * CTX_N + col] =
            __floats2half2_rn(o[nt][0] * inv0, o[nt][1] * inv0);
        *(__half2*)&ctxh[(size_t)row1 * CTX_N + col] =
            __floats2half2_rn(o[nt][2] * inv1, o[nt][3] * inv1);
    }
}

// ---------------------------------------------------------------------------
// Launch pipeline.
// ---------------------------------------------------------------------------
extern "C" void kernel_launch(void* const* d_in, const int* in_sizes, int n_in,
                              void* d_out, int out_size)
{
    const float* hidden = (const float*)d_in[0];
    const int*   pos    = (const int*)d_in[1];
    const float* Wqkv   = (const float*)d_in[2];
    const float* Wo     = (const float*)d_in[3];
    float* out = (float*)d_out;

    float* qkv_d;
    __half *hid_h, *ctx_h, *wqkvT_h, *wqkvT_l, *woT_h, *woT_l;
    __nv_bfloat16 *qh, *ql, *kh, *kl, *vh, *vl;
    cudaGetSymbolAddress((void**)&qkv_d, g_qkv);
    cudaGetSymbolAddress((void**)&hid_h, g_hid_h);
    cudaGetSymbolAddress((void**)&ctx_h, g_ctx_h);
    cudaGetSymbolAddress((void**)&wqkvT_h, g_wqkvT_h);
    cudaGetSymbolAddress((void**)&wqkvT_l, g_wqkvT_l);
    cudaGetSymbolAddress((void**)&woT_h, g_woT_h);
    cudaGetSymbolAddress((void**)&woT_l, g_woT_l);
    cudaGetSymbolAddress((void**)&qh, g_qh);
    cudaGetSymbolAddress((void**)&ql, g_ql);
    cudaGetSymbolAddress((void**)&kh, g_kh);
    cudaGetSymbolAddress((void**)&kl, g_kl);
    cudaGetSymbolAddress((void**)&vh, g_vh);
    cudaGetSymbolAddress((void**)&vl, g_vl);

    cudaFuncSetAttribute(gemm_f16x2_kernel, cudaFuncAttributeMaxDynamicSharedMemorySize,
                         GEMM_SMEM);
    cudaFuncSetAttribute(attn_mma_kernel, cudaFuncAttributeMaxDynamicSharedMemorySize,
                         AT_SMEM);

    conv16_kernel<<<(T_SEQ * HID_DIM) / (256 * 4), 256>>>(hidden, hid_h);
    split_T16_kernel<<<dim3(QKV_N / 32, HID_DIM / 32), dim3(32, 8)>>>(Wqkv, wqkvT_h, wqkvT_l, HID_DIM, QKV_N);
    split_T16_kernel<<<dim3(HID_DIM / 32, CTX_N / 32), dim3(32, 8)>>>(Wo, woT_h, woT_l, CTX_N, HID_DIM);

    gemm_f16x2_kernel<<<dim3(QKV_N / 128, T_SEQ / 128), 128, GEMM_SMEM>>>(
        hid_h, wqkvT_h, wqkvT_l, qkv_d, T_SEQ, QKV_N, HID_DIM);

    rope_split_kernel<<<T_SEQ, 128>>>(qkv_d, pos, qh, ql, kh, kl, vh, vl);

    attn_mma_kernel<<<dim3(T_SEQ / 64, NH), 128, AT_SMEM>>>(
        qh, ql, kh, kl, vh, vl, ctx_h);

    gemm_f16x2_kernel<<<dim3(HID_DIM / 128, T_SEQ / 128), 128, GEMM_SMEM>>>(
        ctx_h, woT_h, woT_l, out, T_SEQ, HID_DIM, CTX_N);
}

// round 14
// speedup vs baseline: 1.0454x; 1.0454x over previous
#include <cuda_runtime.h>
#include <cuda_bf16.h>
#include <cuda_fp16.h>
#include <math.h>
#include <cstdint>
#include <cstddef>

#define T_SEQ 2048
#define HID_DIM 2048
#define NH 16
#define NKV 4
#define HD 128
#define QKV_N ((NH + 2 * NKV) * HD)   // 3072
#define CTX_N (NH * HD)               // 2048
// 1/sqrt(128) * log2(e): scores in log2 domain, softmax via exp2
#define SCALEL2 0.12753139578983588f

// ---------------- scratch (no cudaMalloc allowed) ----------------
__device__ float g_qkv[T_SEQ * QKV_N];
__device__ __half g_hid_h[T_SEQ * HID_DIM];
__device__ __half g_wqkvT_h[QKV_N * HID_DIM];
__device__ __half g_wqkvT_l[QKV_N * HID_DIM];
__device__ __half g_woT_h[HID_DIM * CTX_N];
__device__ __half g_woT_l[HID_DIM * CTX_N];
__device__ __half g_ctx_h[T_SEQ * CTX_N];
// attention operands: q single fp16 (pre-scaled), k/v fp16 hi+lo
__device__ __half g_q16[T_SEQ * NH * HD];
__device__ __half g_k16h[T_SEQ * NKV * HD];
__device__ __half g_k16l[T_SEQ * NKV * HD];
__device__ __half g_v16h[T_SEQ * NKV * HD];
__device__ __half g_v16l[T_SEQ * NKV * HD];

// ---------------- tiny helpers ----------------
__device__ __forceinline__ uint32_t packh(float lo, float hi) {
    uint32_t r;
    asm("cvt.rn.f16x2.f32 %0, %1, %2;" : "=r"(r) : "f"(hi), "f"(lo));
    return r;
}

#define MMA4H(d, a, b0_, b1_)                                                 \
    asm volatile(                                                             \
        "mma.sync.aligned.m16n8k16.row.col.f32.f16.f16.f32 "                  \
        "{%0,%1,%2,%3}, {%4,%5,%6,%7}, {%8,%9}, {%0,%1,%2,%3};\n"             \
        : "+f"((d)[0]), "+f"((d)[1]), "+f"((d)[2]), "+f"((d)[3])              \
        : "r"((a)[0]), "r"((a)[1]), "r"((a)[2]), "r"((a)[3]),                 \
          "r"(b0_), "r"(b1_))

#define LDSM_X4(r0, r1, r2, r3, a)                                            \
    asm volatile("ldmatrix.sync.aligned.m8n8.x4.shared.b16 {%0,%1,%2,%3}, [%4];" \
                 : "=r"(r0), "=r"(r1), "=r"(r2), "=r"(r3) : "r"(a))

#define LDSM_X4_T(r0, r1, r2, r3, a)                                          \
    asm volatile("ldmatrix.sync.aligned.m8n8.x4.trans.shared.b16 {%0,%1,%2,%3}, [%4];" \
                 : "=r"(r0), "=r"(r1), "=r"(r2), "=r"(r3) : "r"(a))

#define CP16(dst, src)                                                        \
    asm volatile("cp.async.cg.shared.global [%0], [%1], 16;\n"                \
                 :: "r"(dst), "l"(src))
#define CP_COMMIT() asm volatile("cp.async.commit_group;\n" ::: "memory")
#define CP_WAIT1()  asm volatile("cp.async.wait_group 1;\n" ::: "memory")

// ---------------------------------------------------------------------------
// fp32 -> fp16 convert.
// ---------------------------------------------------------------------------
__global__ void conv16_kernel(const float* __restrict__ X, __half* __restrict__ Y)
{
    const size_t i = ((size_t)blockIdx.x * blockDim.x + threadIdx.x) * 4;
    float4 v = *(const float4*)&X[i];
    *(__half2*)&Y[i]     = __floats2half2_rn(v.x, v.y);
    *(__half2*)&Y[i + 2] = __floats2half2_rn(v.z, v.w);
}

// ---------------------------------------------------------------------------
// Split + transpose: W[Kd][N] fp32 -> Wt hi/lo fp16 [N][Kd].
// ---------------------------------------------------------------------------
__global__ void split_T16_kernel(const float* __restrict__ W,
                                 __half* __restrict__ hi, __half* __restrict__ lo,
                                 int Kd, int N)
{
    __shared__ float tile[32][33];
    const int n0 = blockIdx.x * 32;
    const int k0 = blockIdx.y * 32;
    const int tx = threadIdx.x, ty = threadIdx.y;
#pragma unroll
    for (int i = 0; i < 32; i += 8)
        tile[ty + i][tx] = W[(size_t)(k0 + ty + i) * N + n0 + tx];
    __syncthreads();
#pragma unroll
    for (int i = 0; i < 32; i += 8) {
        const float v = tile[tx][ty + i];
        const __half h = __float2half_rn(v);
        const size_t o = (size_t)(n0 + ty + i) * Kd + k0 + tx;
        hi[o] = h;
        lo[o] = __float2half_rn(v - __half2float(h));
    }
}

// ---------------------------------------------------------------------------
// fp16x2 GEMM (unchanged from round 12).
// ---------------------------------------------------------------------------
#define TCAB 8192
#define SLOTB (3 * TCAB)
#define GEMM_SMEM (3 * SLOTB)

__global__ __launch_bounds__(128, 2) void gemm_f16x2_kernel(
    const __half* __restrict__ Ah,
    const __half* __restrict__ Bh, const __half* __restrict__ Bl,
    float* __restrict__ C, int M, int N, int Kd)
{
    extern __shared__ __half gsm[];
    const uint32_t smem0 = (uint32_t)__cvta_generic_to_shared(gsm);

    const int tid  = threadIdx.x;
    const int lane = tid & 31;
    const int wid  = tid >> 5;
    const int g    = lane >> 2;
    const int cq   = lane & 3;
    const int wm   = wid & 1;
    const int wn   = wid >> 1;
    const int row0 = blockIdx.y * 128;
    const int col0 = blockIdx.x * 128;

    const int lm  = lane >> 3;
    const int row_local = ((lm & 1) << 3) + (lane & 7);
    const int chi = lm >> 1;
    const int xorv = (row_local >> 1) & 3;
    const int lo0 = row_local * 64 + (((0 | chi) ^ xorv) << 4);
    const int lo1 = row_local * 64 + (((2 | chi) ^ xorv) << 4);

    uint32_t dsw[4];
    int goff[4];
#pragma unroll
    for (int i = 0; i < 4; i++) {
        const int c = i * 128 + tid;
        const int r = c >> 2, cc = c & 3;
        dsw[i] = r * 64 + ((cc ^ ((r >> 1) & 3)) << 4);
        goff[i] = r * Kd + cc * 8;
    }

    const __half* pAh = Ah + (size_t)row0 * Kd;
    const __half* pBh = Bh + (size_t)col0 * Kd;
    const __half* pBl = Bl + (size_t)col0 * Kd;

    const int nK = Kd >> 5;

    float acc[4][8][4];
#pragma unroll
    for (int i = 0; i < 4; i++)
#pragma unroll
        for (int j = 0; j < 8; j++)
#pragma unroll
            for (int e = 0; e < 4; e++) acc[i][j][e] = 0.0f;

#pragma unroll
    for (int pf = 0; pf < 2; pf++) {
        const int k0 = pf * 32;
        const uint32_t sb = smem0 + pf * SLOTB;
#pragma unroll
        for (int i = 0; i < 4; i++) {
            CP16(sb + dsw[i],            pAh + goff[i] + k0);
            CP16(sb + TCAB + dsw[i],     pBh + goff[i] + k0);
            CP16(sb + 2 * TCAB + dsw[i], pBl + goff[i] + k0);
        }
        CP_COMMIT();
    }

    int scur = 0, spre = 2;
    for (int kt = 0; kt < nK; kt++) {
        CP_WAIT1();
        __syncthreads();

        if (kt + 2 < nK) {
            const int k0 = (kt + 2) * 32;
            const uint32_t db = smem0 + spre * SLOTB;
#pragma unroll
            for (int i = 0; i < 4; i++) {
                CP16(db + dsw[i],            pAh + goff[i] + k0);
                CP16(db + TCAB + dsw[i],     pBh + goff[i] + k0);
                CP16(db + 2 * TCAB + dsw[i], pBl + goff[i] + k0);
            }
        }
        CP_COMMIT();

        const uint32_t sb  = smem0 + scur * SLOTB;
        const uint32_t sAh = sb;
        const uint32_t sBh = sb + TCAB;
        const uint32_t sBl = sb + 2 * TCAB;

#pragma unroll
        for (int ks2 = 0; ks2 < 2; ks2++) {
            const int lo = ks2 ? lo1 : lo0;
            uint32_t ah[4][4], bh[8][2], bl[8][2];
#pragma unroll
            for (int mt = 0; mt < 4; mt++) {
                const int off = (wm * 64 + mt * 16) * 64 + lo;
                LDSM_X4(ah[mt][0], ah[mt][1], ah[mt][2], ah[mt][3], sAh + off);
            }
#pragma unroll
            for (int np = 0; np < 4; np++) {
                const int off = (wn * 64 + np * 16) * 64 + lo;
                uint32_t t0, t1, t2, t3;
                LDSM_X4(t0, t1, t2, t3, sBh + off);
                bh[2 * np][0] = t0; bh[2 * np + 1][0] = t1;
                bh[2 * np][1] = t2; bh[2 * np + 1][1] = t3;
                LDSM_X4(t0, t1, t2, t3, sBl + off);
                bl[2 * np][0] = t0; bl[2 * np + 1][0] = t1;
                bl[2 * np][1] = t2; bl[2 * np + 1][1] = t3;
            }
#pragma unroll
            for (int mt = 0; mt < 4; mt++)
#pragma unroll
                for (int nt = 0; nt < 8; nt++) MMA4H(acc[mt][nt], ah[mt], bh[nt][0], bh[nt][1]);
#pragma unroll
            for (int mt = 0; mt < 4; mt++)
#pragma unroll
                for (int nt = 0; nt < 8; nt++) MMA4H(acc[mt][nt], ah[mt], bl[nt][0], bl[nt][1]);
        }

        scur = (scur == 2) ? 0 : scur + 1;
        spre = (spre == 2) ? 0 : spre + 1;
    }

#pragma unroll
    for (int mt = 0; mt < 4; mt++) {
        const int r0 = row0 + wm * 64 + mt * 16 + g;
#pragma unroll
        for (int nt = 0; nt < 8; nt++) {
            const int cb = col0 + wn * 64 + nt * 8 + 2 * cq;
            *(float2*)&C[(size_t)r0 * N + cb]       = make_float2(acc[mt][nt][0], acc[mt][nt][1]);
            *(float2*)&C[(size_t)(r0 + 8) * N + cb] = make_float2(acc[mt][nt][2], acc[mt][nt][3]);
        }
    }
}

// ---------------------------------------------------------------------------
// RoPE + scale(log2e) + fp16 outputs: q single, k/v hi+lo.
// ---------------------------------------------------------------------------
__global__ void rope_split_kernel(const float* __restrict__ qkv,
                                  const int* __restrict__ pos,
                                  __half* __restrict__ q16,
                                  __half* __restrict__ k16h, __half* __restrict__ k16l,
                                  __half* __restrict__ v16h, __half* __restrict__ v16l)
{
    const int t = blockIdx.x;
    const int tid = threadIdx.x;
    const float p = (float)pos[t];
    const float* base = qkv + (size_t)t * QKV_N;

#pragma unroll
    for (int it = 0; it < 8; it++) {
        const int item = it * 128 + tid;
        const int head = item >> 6, j = item & 63;
        const float invf = powf(10000.0f, -((float)j) * (1.0f / 64.0f));
        float s, c; sincosf(p * invf, &s, &c);
        const float x1 = base[head * HD + j];
        const float x2 = base[head * HD + j + 64];
        const size_t o = (size_t)t * (NH * HD) + head * HD + j;
        q16[o]      = __float2half_rn((x1 * c - x2 * s) * SCALEL2);
        q16[o + 64] = __float2half_rn((x2 * c + x1 * s) * SCALEL2);
    }
#pragma unroll
    for (int it = 0; it < 2; it++) {
        const int item = it * 128 + tid;
        const int head = item >> 6, j = item & 63;
        const float invf = powf(10000.0f, -((float)j) * (1.0f / 64.0f));
        float s, c; sincosf(p * invf, &s, &c);
        const float x1 = base[NH * HD + head * HD + j];
        const float x2 = base[NH * HD + head * HD + j + 64];
        const float y1 = x1 * c - x2 * s;
        const float y2 = x2 * c + x1 * s;
        const size_t o = (size_t)t * (NKV * HD) + head * HD + j;
        __half h1 = __float2half_rn(y1), h2 = __float2half_rn(y2);
        k16h[o] = h1;      k16l[o]      = __float2half_rn(y1 - __half2float(h1));
        k16h[o + 64] = h2; k16l[o + 64] = __float2half_rn(y2 - __half2float(h2));
    }
#pragma unroll
    for (int it = 0; it < 4; it++) {
        const int idx = it * 128 + tid;
        const float x = base[(NH + NKV) * HD + idx];
        const size_t o = (size_t)t * (NKV * HD) + idx;
        __half h = __float2half_rn(x);
        v16h[o] = h; v16l[o] = __float2half_rn(x - __half2float(h));
    }
}

// ---------------------------------------------------------------------------
// Flash attention fp16x2: BQ=BK=64, 128 threads, 69632B smem (3 CTAs/SM).
// S = Qh*Kh + Qh*Kl; O += Ph*Vh + Ph*Vl. exp2-domain softmax.
// r12 structure (synchronous loads, 2 barriers/block) — proven best.
// ---------------------------------------------------------------------------
#define PITCH 136
#define PITCHB (PITCH * 2)
#define AT_SMEM (4 * 64 * PITCH * 2)

__global__ __launch_bounds__(128) void attn_mma_kernel(
    const __half* __restrict__ q16,
    const __half* __restrict__ k16h, const __half* __restrict__ k16l,
    const __half* __restrict__ v16h, const __half* __restrict__ v16l,
    __half* __restrict__ ctxh)
{
    extern __shared__ __half sm16[];
    __half* Kh = sm16;
    __half* Kl = sm16 + 64 * PITCH;
    __half* Vh = sm16 + 2 * 64 * PITCH;
    __half* Vl = sm16 + 3 * 64 * PITCH;

    const int tid  = threadIdx.x;
    const int lane = tid & 31;
    const int w    = tid >> 5;
    const int gr   = lane >> 2;
    const int tq   = lane & 3;
    const int qb   = (int)gridDim.x - 1 - (int)blockIdx.x;
    const int h    = blockIdx.y;
    const int kvh  = h >> 2;
    const int q0   = qb * 64;

    const int lm = lane >> 3;
    const int laneoff = (((lm & 1) << 3) + (lane & 7)) * PITCHB + ((lm >> 1) << 3) * 2;

    const uint32_t sKh = (uint32_t)__cvta_generic_to_shared(Kh);
    const uint32_t sKl = (uint32_t)__cvta_generic_to_shared(Kl);
    const uint32_t sVh = (uint32_t)__cvta_generic_to_shared(Vh);
    const uint32_t sVl = (uint32_t)__cvta_generic_to_shared(Vl);

    // ---- stage Q (single fp16) into Kh area, extract fragments ----
#pragma unroll
    for (int it = 0; it < 8; it++) {
        const int idx = it * 128 + tid;
        const int row = idx >> 4;
        const int cc  = (idx & 15) * 8;
        const size_t gs = (size_t)(q0 + row) * (NH * HD) + h * HD + cc;
        *(uint4*)&Kh[row * PITCH + cc] = *(const uint4*)&q16[gs];
    }
    __syncthreads();

    uint32_t qf[8][4];
#pragma unroll
    for (int ks = 0; ks < 8; ks++)
        LDSM_X4(qf[ks][0], qf[ks][1], qf[ks][2], qf[ks][3],
                sKh + (16 * w) * PITCHB + (16 * ks) * 2 + laneoff);

    float o[16][4];
#pragma unroll
    for (int i = 0; i < 16; i++)
#pragma unroll
        for (int e = 0; e < 4; e++) o[i][e] = 0.0f;
    float mrun0 = -1e30f, mrun1 = -1e30f, lrun0 = 0.0f, lrun1 = 0.0f;

    for (int kb = 0; kb <= qb; kb++) {
        const int k0 = kb * 64;
        __syncthreads();   // protect prior reads (and Q staging on iter 0)

#pragma unroll
        for (int it = 0; it < 8; it++) {
            const int idx = it * 128 + tid;
            const int row = idx >> 4;
            const int cc  = (idx & 15) * 8;
            const size_t gs = (size_t)(k0 + row) * (NKV * HD) + kvh * HD + cc;
            const int ss = row * PITCH + cc;
            *(uint4*)&Kh[ss] = *(const uint4*)&k16h[gs];
            *(uint4*)&Kl[ss] = *(const uint4*)&k16l[gs];
            *(uint4*)&Vh[ss] = *(const uint4*)&v16h[gs];
            *(uint4*)&Vl[ss] = *(const uint4*)&v16l[gs];
        }
        __syncthreads();

        // ---- S = Q @ K^T (fp16x2: Qh*Kh + Qh*Kl) ----
        float s[8][4];
#pragma unroll
        for (int i = 0; i < 8; i++)
#pragma unroll
            for (int e = 0; e < 4; e++) s[i][e] = 0.0f;

#pragma unroll
        for (int nt2 = 0; nt2 < 4; nt2++) {
#pragma unroll
            for (int ks = 0; ks < 8; ks++) {
                const int toff = (16 * nt2) * PITCHB + (16 * ks) * 2 + laneoff;
                uint32_t kh0, kh1, kh2, kh3, kl0, kl1, kl2, kl3;
                LDSM_X4(kh0, kh1, kh2, kh3, sKh + toff);
                LDSM_X4(kl0, kl1, kl2, kl3, sKl + toff);
                MMA4H(s[2 * nt2],     qf[ks], kh0, kh2);
                MMA4H(s[2 * nt2],     qf[ks], kl0, kl2);
                MMA4H(s[2 * nt2 + 1], qf[ks], kh1, kh3);
                MMA4H(s[2 * nt2 + 1], qf[ks], kl1, kl3);
            }
        }

        // ---- causal mask (diagonal block only) ----
        if (kb == qb) {
            const int lr0 = 16 * w + gr;
#pragma unroll
            for (int nt = 0; nt < 8; nt++) {
                const int c0 = 8 * nt + 2 * tq;
                if (c0     > lr0)     s[nt][0] = -1e30f;
                if (c0 + 1 > lr0)     s[nt][1] = -1e30f;
                if (c0     > lr0 + 8) s[nt][2] = -1e30f;
                if (c0 + 1 > lr0 + 8) s[nt][3] = -1e30f;
            }
        }

        // ---- online softmax (exp2 domain) ----
        float m0l = -1e30f, m1l = -1e30f;
#pragma unroll
        for (int nt = 0; nt < 8; nt++) {
            m0l = fmaxf(m0l, fmaxf(s[nt][0], s[nt][1]));
            m1l = fmaxf(m1l, fmaxf(s[nt][2], s[nt][3]));
        }
        m0l = fmaxf(m0l, __shfl_xor_sync(0xffffffffu, m0l, 1));
        m0l = fmaxf(m0l, __shfl_xor_sync(0xffffffffu, m0l, 2));
        m1l = fmaxf(m1l, __shfl_xor_sync(0xffffffffu, m1l, 1));
        m1l = fmaxf(m1l, __shfl_xor_sync(0xffffffffu, m1l, 2));
        const float mn0 = fmaxf(mrun0, m0l);
        const float mn1 = fmaxf(mrun1, m1l);
        const float corr0 = exp2f(mrun0 - mn0);
        const float corr1 = exp2f(mrun1 - mn1);
        mrun0 = mn0; mrun1 = mn1;
        float sum0 = 0.0f, sum1 = 0.0f;
#pragma unroll
        for (int nt = 0; nt < 8; nt++) {
            s[nt][0] = exp2f(s[nt][0] - mn0);
            s[nt][1] = exp2f(s[nt][1] - mn0);
            s[nt][2] = exp2f(s[nt][2] - mn1);
            s[nt][3] = exp2f(s[nt][3] - mn1);
            sum0 += s[nt][0] + s[nt][1];
            sum1 += s[nt][2] + s[nt][3];
        }
        sum0 += __shfl_xor_sync(0xffffffffu, sum0, 1);
        sum0 += __shfl_xor_sync(0xffffffffu, sum0, 2);
        sum1 += __shfl_xor_sync(0xffffffffu, sum1, 1);
        sum1 += __shfl_xor_sync(0xffffffffu, sum1, 2);
        lrun0 = lrun0 * corr0 + sum0;
        lrun1 = lrun1 * corr1 + sum1;

#pragma unroll
        for (int nt = 0; nt < 16; nt++) {
            o[nt][0] *= corr0; o[nt][1] *= corr0;
            o[nt][2] *= corr1; o[nt][3] *= corr1;
        }

        // ---- O += P @ V (fp16x2: Ph*Vh + Ph*Vl) ----
#pragma unroll
        for (int kvs = 0; kvs < 4; kvs++) {
            uint32_t ph[4];
            ph[0] = packh(s[2 * kvs][0], s[2 * kvs][1]);
            ph[1] = packh(s[2 * kvs][2], s[2 * kvs][3]);
            ph[2] = packh(s[2 * kvs + 1][0], s[2 * kvs + 1][1]);
            ph[3] = packh(s[2 * kvs + 1][2], s[2 * kvs + 1][3]);
#pragma unroll
            for (int dn2 = 0; dn2 < 8; dn2++) {
                const int toff = (16 * kvs) * PITCHB + (16 * dn2) * 2 + laneoff;
                uint32_t vh0, vh1, vh2, vh3, vl0, vl1, vl2, vl3;
                LDSM_X4_T(vh0, vh1, vh2, vh3, sVh + toff);
                LDSM_X4_T(vl0, vl1, vl2, vl3, sVl + toff);
                MMA4H(o[2 * dn2],     ph, vh0, vh1);
                MMA4H(o[2 * dn2],     ph, vl0, vl1);
                MMA4H(o[2 * dn2 + 1], ph, vh2, vh3);
                MMA4H(o[2 * dn2 + 1], ph, vl2, vl3);
            }
        }
    }

    // ---- epilogue: normalize, emit fp16 ctx ----
    const float inv0 = 1.0f / lrun0;
    const float inv1 = 1.0f / lrun1;
    const int row0 = q0 + 16 * w + gr;
    const int row1 = row0 + 8;
#pragma unroll
    for (int nt = 0; nt < 16; nt++) {
        const int col = h * HD + 8 * nt + 2 * tq;
        *(__half2*)&ctxh[(size_t)row0 * CTX_N + col] =
            __floats2half2_rn(o[nt][0] * inv0, o[nt][1] * inv0);
        *(__half2*)&ctxh[(size_t)row1 * CTX_N + col] =
            __floats2half2_rn(o[nt][2] * inv1, o[nt][3] * inv1);
    }
}

// ---------------------------------------------------------------------------
// Launch pipeline.
// ---------------------------------------------------------------------------
extern "C" void kernel_launch(void* const* d_in, const int* in_sizes, int n_in,
                              void* d_out, int out_size)
{
    const float* hidden = (const float*)d_in[0];
    const int*   pos    = (const int*)d_in[1];
    const float* Wqkv   = (const float*)d_in[2];
    const float* Wo     = (const float*)d_in[3];
    float* out = (float*)d_out;

    float* qkv_d;
    __half *hid_h, *ctx_h, *wqkvT_h, *wqkvT_l, *woT_h, *woT_l;
    __half *q16, *k16h, *k16l, *v16h, *v16l;
    cudaGetSymbolAddress((void**)&qkv_d, g_qkv);
    cudaGetSymbolAddress((void**)&hid_h, g_hid_h);
    cudaGetSymbolAddress((void**)&ctx_h, g_ctx_h);
    cudaGetSymbolAddress((void**)&wqkvT_h, g_wqkvT_h);
    cudaGetSymbolAddress((void**)&wqkvT_l, g_wqkvT_l);
    cudaGetSymbolAddress((void**)&woT_h, g_woT_h);
    cudaGetSymbolAddress((void**)&woT_l, g_woT_l);
    cudaGetSymbolAddress((void**)&q16, g_q16);
    cudaGetSymbolAddress((void**)&k16h, g_k16h);
    cudaGetSymbolAddress((void**)&k16l, g_k16l);
    cudaGetSymbolAddress((void**)&v16h, g_v16h);
    cudaGetSymbolAddress((void**)&v16l, g_v16l);

    cudaFuncSetAttribute(gemm_f16x2_kernel, cudaFuncAttributeMaxDynamicSharedMemorySize,
                         GEMM_SMEM);
    cudaFuncSetAttribute(attn_mma_kernel, cudaFuncAttributeMaxDynamicSharedMemorySize,
                         AT_SMEM);

    conv16_kernel<<<(T_SEQ * HID_DIM) / (256 * 4), 256>>>(hidden, hid_h);
    split_T16_kernel<<<dim3(QKV_N / 32, HID_DIM / 32), dim3(32, 8)>>>(Wqkv, wqkvT_h, wqkvT_l, HID_DIM, QKV_N);
    split_T16_kernel<<<dim3(HID_DIM / 32, CTX_N / 32), dim3(32, 8)>>>(Wo, woT_h, woT_l, CTX_N, HID_DIM);

    // 1) qkv = hidden @ Wqkv  (fp16x2 tensor-core GEMM)
    gemm_f16x2_kernel<<<dim3(QKV_N / 128, T_SEQ / 128), 128, GEMM_SMEM>>>(
        hid_h, wqkvT_h, wqkvT_l, qkv_d, T_SEQ, QKV_N, HID_DIM);

    // 2) RoPE + scale(log2e) + fp16 split
    rope_split_kernel<<<T_SEQ, 128>>>(qkv_d, pos, q16, k16h, k16l, v16h, v16l);

    // 3) causal GQA flash attention (fp16x2 tensor cores)
    attn_mma_kernel<<<dim3(T_SEQ / 64, NH), 128, AT_SMEM>>>(
        q16, k16h, k16l, v16h, v16l, ctx_h);

    // 4) out = ctx @ Wo  (fp16x2 tensor-core GEMM)
    gemm_f16x2_kernel<<<dim3(HID_DIM / 128, T_SEQ / 128), 128, GEMM_SMEM>>>(
        ctx_h, woT_h, woT_l, out, T_SEQ, HID_DIM, CTX_N);
}

// round 15
// speedup vs baseline: 1.2391x; 1.1852x over previous
#include <cuda_runtime.h>
#include <cuda_bf16.h>
#include <cuda_fp16.h>
#include <math.h>
#include <cstdint>
#include <cstddef>

#define T_SEQ 2048
#define HID_DIM 2048
#define NH 16
#define NKV 4
#define HD 128
#define QKV_N ((NH + 2 * NKV) * HD)   // 3072
#define CTX_N (NH * HD)               // 2048
// 1/sqrt(128) * log2(e)
#define SCALEL2 0.12753139578983588f

// ---------------- scratch (no cudaMalloc allowed) ----------------
__device__ float g_qkv[T_SEQ * QKV_N];
__device__ __half g_hid_h[T_SEQ * HID_DIM];
__device__ __half g_wqkvT_h[QKV_N * HID_DIM];
__device__ __half g_wqkvT_l[QKV_N * HID_DIM];
__device__ __half g_woT_h[HID_DIM * CTX_N];
__device__ __half g_ctx_h[T_SEQ * CTX_N];
__device__ __half g_q16[T_SEQ * NH * HD];
__device__ __half g_k16h[T_SEQ * NKV * HD];
__device__ __half g_k16l[T_SEQ * NKV * HD];
__device__ __half g_v16h[T_SEQ * NKV * HD];

// ---------------- tiny helpers ----------------
__device__ __forceinline__ uint32_t packh(float lo, float hi) {
    uint32_t r;
    asm("cvt.rn.f16x2.f32 %0, %1, %2;" : "=r"(r) : "f"(hi), "f"(lo));
    return r;
}

#define MMA4H(d, a, b0_, b1_)                                                 \
    asm volatile(                                                             \
        "mma.sync.aligned.m16n8k16.row.col.f32.f16.f16.f32 "                  \
        "{%0,%1,%2,%3}, {%4,%5,%6,%7}, {%8,%9}, {%0,%1,%2,%3};\n"             \
        : "+f"((d)[0]), "+f"((d)[1]), "+f"((d)[2]), "+f"((d)[3])              \
        : "r"((a)[0]), "r"((a)[1]), "r"((a)[2]), "r"((a)[3]),                 \
          "r"(b0_), "r"(b1_))

#define LDSM_X4(r0, r1, r2, r3, a)                                            \
    asm volatile("ldmatrix.sync.aligned.m8n8.x4.shared.b16 {%0,%1,%2,%3}, [%4];" \
                 : "=r"(r0), "=r"(r1), "=r"(r2), "=r"(r3) : "r"(a))

#define LDSM_X4_T(r0, r1, r2, r3, a)                                          \
    asm volatile("ldmatrix.sync.aligned.m8n8.x4.trans.shared.b16 {%0,%1,%2,%3}, [%4];" \
                 : "=r"(r0), "=r"(r1), "=r"(r2), "=r"(r3) : "r"(a))

#define CP16(dst, src)                                                        \
    asm volatile("cp.async.cg.shared.global [%0], [%1], 16;\n"                \
                 :: "r"(dst), "l"(src))
#define CP_COMMIT() asm volatile("cp.async.commit_group;\n" ::: "memory")
#define CP_WAIT1()  asm volatile("cp.async.wait_group 1;\n" ::: "memory")

// ---------------------------------------------------------------------------
// fp32 -> fp16 convert.
// ---------------------------------------------------------------------------
__global__ void conv16_kernel(const float* __restrict__ X, __half* __restrict__ Y)
{
    const size_t i = ((size_t)blockIdx.x * blockDim.x + threadIdx.x) * 4;
    float4 v = *(const float4*)&X[i];
    *(__half2*)&Y[i]     = __floats2half2_rn(v.x, v.y);
    *(__half2*)&Y[i + 2] = __floats2half2_rn(v.z, v.w);
}

// ---------------------------------------------------------------------------
// Split + transpose: W[Kd][N] fp32 -> Wt hi/lo fp16 [N][Kd].
// ---------------------------------------------------------------------------
__global__ void split_T16_kernel(const float* __restrict__ W,
                                 __half* __restrict__ hi, __half* __restrict__ lo,
                                 int Kd, int N)
{
    __shared__ float tile[32][33];
    const int n0 = blockIdx.x * 32;
    const int k0 = blockIdx.y * 32;
    const int tx = threadIdx.x, ty = threadIdx.y;
#pragma unroll
    for (int i = 0; i < 32; i += 8)
        tile[ty + i][tx] = W[(size_t)(k0 + ty + i) * N + n0 + tx];
    __syncthreads();
#pragma unroll
    for (int i = 0; i < 32; i += 8) {
        const float v = tile[tx][ty + i];
        const __half h = __float2half_rn(v);
        const size_t o = (size_t)(n0 + ty + i) * Kd + k0 + tx;
        hi[o] = h;
        lo[o] = __float2half_rn(v - __half2float(h));
    }
}

// ---------------------------------------------------------------------------
// Transpose only: W[Kd][N] fp32 -> Wt fp16 [N][Kd] (single precision level).
// ---------------------------------------------------------------------------
__global__ void trans_T16_kernel(const float* __restrict__ W,
                                 __half* __restrict__ hi, int Kd, int N)
{
    __shared__ float tile[32][33];
    const int n0 = blockIdx.x * 32;
    const int k0 = blockIdx.y * 32;
    const int tx = threadIdx.x, ty = threadIdx.y;
#pragma unroll
    for (int i = 0; i < 32; i += 8)
        tile[ty + i][tx] = W[(size_t)(k0 + ty + i) * N + n0 + tx];
    __syncthreads();
#pragma unroll
    for (int i = 0; i < 32; i += 8)
        hi[(size_t)(n0 + ty + i) * Kd + k0 + tx] = __float2half_rn(tile[tx][ty + i]);
}

// ---------------------------------------------------------------------------
// fp16x2 GEMM (two B passes) — GEMM1. Unchanged from round 12.
// ---------------------------------------------------------------------------
#define TCAB 8192
#define SLOTB2 (3 * TCAB)
#define GEMM_SMEM2 (3 * SLOTB2)       // 73728

__global__ __launch_bounds__(128, 2) void gemm_f16x2_kernel(
    const __half* __restrict__ Ah,
    const __half* __restrict__ Bh, const __half* __restrict__ Bl,
    float* __restrict__ C, int M, int N, int Kd)
{
    extern __shared__ __half gsm[];
    const uint32_t smem0 = (uint32_t)__cvta_generic_to_shared(gsm);

    const int tid  = threadIdx.x;
    const int lane = tid & 31;
    const int wid  = tid >> 5;
    const int g    = lane >> 2;
    const int cq   = lane & 3;
    const int wm   = wid & 1;
    const int wn   = wid >> 1;
    const int row0 = blockIdx.y * 128;
    const int col0 = blockIdx.x * 128;

    const int lm  = lane >> 3;
    const int row_local = ((lm & 1) << 3) + (lane & 7);
    const int chi = lm >> 1;
    const int xorv = (row_local >> 1) & 3;
    const int lo0 = row_local * 64 + (((0 | chi) ^ xorv) << 4);
    const int lo1 = row_local * 64 + (((2 | chi) ^ xorv) << 4);

    uint32_t dsw[4];
    int goff[4];
#pragma unroll
    for (int i = 0; i < 4; i++) {
        const int c = i * 128 + tid;
        const int r = c >> 2, cc = c & 3;
        dsw[i] = r * 64 + ((cc ^ ((r >> 1) & 3)) << 4);
        goff[i] = r * Kd + cc * 8;
    }

    const __half* pAh = Ah + (size_t)row0 * Kd;
    const __half* pBh = Bh + (size_t)col0 * Kd;
    const __half* pBl = Bl + (size_t)col0 * Kd;

    const int nK = Kd >> 5;

    float acc[4][8][4];
#pragma unroll
    for (int i = 0; i < 4; i++)
#pragma unroll
        for (int j = 0; j < 8; j++)
#pragma unroll
            for (int e = 0; e < 4; e++) acc[i][j][e] = 0.0f;

#pragma unroll
    for (int pf = 0; pf < 2; pf++) {
        const int k0 = pf * 32;
        const uint32_t sb = smem0 + pf * SLOTB2;
#pragma unroll
        for (int i = 0; i < 4; i++) {
            CP16(sb + dsw[i],            pAh + goff[i] + k0);
            CP16(sb + TCAB + dsw[i],     pBh + goff[i] + k0);
            CP16(sb + 2 * TCAB + dsw[i], pBl + goff[i] + k0);
        }
        CP_COMMIT();
    }

    int scur = 0, spre = 2;
    for (int kt = 0; kt < nK; kt++) {
        CP_WAIT1();
        __syncthreads();

        if (kt + 2 < nK) {
            const int k0 = (kt + 2) * 32;
            const uint32_t db = smem0 + spre * SLOTB2;
#pragma unroll
            for (int i = 0; i < 4; i++) {
                CP16(db + dsw[i],            pAh + goff[i] + k0);
                CP16(db + TCAB + dsw[i],     pBh + goff[i] + k0);
                CP16(db + 2 * TCAB + dsw[i], pBl + goff[i] + k0);
            }
        }
        CP_COMMIT();

        const uint32_t sb  = smem0 + scur * SLOTB2;
        const uint32_t sAh = sb;
        const uint32_t sBh = sb + TCAB;
        const uint32_t sBl = sb + 2 * TCAB;

#pragma unroll
        for (int ks2 = 0; ks2 < 2; ks2++) {
            const int lo = ks2 ? lo1 : lo0;
            uint32_t ah[4][4], bh[8][2], bl[8][2];
#pragma unroll
            for (int mt = 0; mt < 4; mt++) {
                const int off = (wm * 64 + mt * 16) * 64 + lo;
                LDSM_X4(ah[mt][0], ah[mt][1], ah[mt][2], ah[mt][3], sAh + off);
            }
#pragma unroll
            for (int np = 0; np < 4; np++) {
                const int off = (wn * 64 + np * 16) * 64 + lo;
                uint32_t t0, t1, t2, t3;
                LDSM_X4(t0, t1, t2, t3, sBh + off);
                bh[2 * np][0] = t0; bh[2 * np + 1][0] = t1;
                bh[2 * np][1] = t2; bh[2 * np + 1][1] = t3;
                LDSM_X4(t0, t1, t2, t3, sBl + off);
                bl[2 * np][0] = t0; bl[2 * np + 1][0] = t1;
                bl[2 * np][1] = t2; bl[2 * np + 1][1] = t3;
            }
#pragma unroll
            for (int mt = 0; mt < 4; mt++)
#pragma unroll
                for (int nt = 0; nt < 8; nt++) MMA4H(acc[mt][nt], ah[mt], bh[nt][0], bh[nt][1]);
#pragma unroll
            for (int mt = 0; mt < 4; mt++)
#pragma unroll
                for (int nt = 0; nt < 8; nt++) MMA4H(acc[mt][nt], ah[mt], bl[nt][0], bl[nt][1]);
        }

        scur = (scur == 2) ? 0 : scur + 1;
        spre = (spre == 2) ? 0 : spre + 1;
    }

#pragma unroll
    for (int mt = 0; mt < 4; mt++) {
        const int r0 = row0 + wm * 64 + mt * 16 + g;
#pragma unroll
        for (int nt = 0; nt < 8; nt++) {
            const int cb = col0 + wn * 64 + nt * 8 + 2 * cq;
            *(float2*)&C[(size_t)r0 * N + cb]       = make_float2(acc[mt][nt][0], acc[mt][nt][1]);
            *(float2*)&C[(size_t)(r0 + 8) * N + cb] = make_float2(acc[mt][nt][2], acc[mt][nt][3]);
        }
    }
}

// ---------------------------------------------------------------------------
// fp16x1 GEMM (single B) — GEMM2. 2-array stages, 3 slots, 3 CTAs/SM.
// ---------------------------------------------------------------------------
#define SLOTB1 (2 * TCAB)
#define GEMM_SMEM1 (3 * SLOTB1)       // 49152

__global__ __launch_bounds__(128, 3) void gemm_f16x1_kernel(
    const __half* __restrict__ Ah, const __half* __restrict__ Bh,
    float* __restrict__ C, int M, int N, int Kd)
{
    extern __shared__ __half gsm[];
    const uint32_t smem0 = (uint32_t)__cvta_generic_to_shared(gsm);

    const int tid  = threadIdx.x;
    const int lane = tid & 31;
    const int wid  = tid >> 5;
    const int g    = lane >> 2;
    const int cq   = lane & 3;
    const int wm   = wid & 1;
    const int wn   = wid >> 1;
    const int row0 = blockIdx.y * 128;
    const int col0 = blockIdx.x * 128;

    const int lm  = lane >> 3;
    const int row_local = ((lm & 1) << 3) + (lane & 7);
    const int chi = lm >> 1;
    const int xorv = (row_local >> 1) & 3;
    const int lo0 = row_local * 64 + (((0 | chi) ^ xorv) << 4);
    const int lo1 = row_local * 64 + (((2 | chi) ^ xorv) << 4);

    uint32_t dsw[4];
    int goff[4];
#pragma unroll
    for (int i = 0; i < 4; i++) {
        const int c = i * 128 + tid;
        const int r = c >> 2, cc = c & 3;
        dsw[i] = r * 64 + ((cc ^ ((r >> 1) & 3)) << 4);
        goff[i] = r * Kd + cc * 8;
    }

    const __half* pAh = Ah + (size_t)row0 * Kd;
    const __half* pBh = Bh + (size_t)col0 * Kd;

    const int nK = Kd >> 5;

    float acc[4][8][4];
#pragma unroll
    for (int i = 0; i < 4; i++)
#pragma unroll
        for (int j = 0; j < 8; j++)
#pragma unroll
            for (int e = 0; e < 4; e++) acc[i][j][e] = 0.0f;

#pragma unroll
    for (int pf = 0; pf < 2; pf++) {
        const int k0 = pf * 32;
        const uint32_t sb = smem0 + pf * SLOTB1;
#pragma unroll
        for (int i = 0; i < 4; i++) {
            CP16(sb + dsw[i],        pAh + goff[i] + k0);
            CP16(sb + TCAB + dsw[i], pBh + goff[i] + k0);
        }
        CP_COMMIT();
    }

    int scur = 0, spre = 2;
    for (int kt = 0; kt < nK; kt++) {
        CP_WAIT1();
        __syncthreads();

        if (kt + 2 < nK) {
            const int k0 = (kt + 2) * 32;
            const uint32_t db = smem0 + spre * SLOTB1;
#pragma unroll
            for (int i = 0; i < 4; i++) {
                CP16(db + dsw[i],        pAh + goff[i] + k0);
                CP16(db + TCAB + dsw[i], pBh + goff[i] + k0);
            }
        }
        CP_COMMIT();

        const uint32_t sb  = smem0 + scur * SLOTB1;
        const uint32_t sAh = sb;
        const uint32_t sBh = sb + TCAB;

#pragma unroll
        for (int ks2 = 0; ks2 < 2; ks2++) {
            const int lo = ks2 ? lo1 : lo0;
            uint32_t ah[4][4], bh[8][2];
#pragma unroll
            for (int mt = 0; mt < 4; mt++) {
                const int off = (wm * 64 + mt * 16) * 64 + lo;
                LDSM_X4(ah[mt][0], ah[mt][1], ah[mt][2], ah[mt][3], sAh + off);
            }
#pragma unroll
            for (int np = 0; np < 4; np++) {
                const int off = (wn * 64 + np * 16) * 64 + lo;
                uint32_t t0, t1, t2, t3;
                LDSM_X4(t0, t1, t2, t3, sBh + off);
                bh[2 * np][0] = t0; bh[2 * np + 1][0] = t1;
                bh[2 * np][1] = t2; bh[2 * np + 1][1] = t3;
            }
#pragma unroll
            for (int mt = 0; mt < 4; mt++)
#pragma unroll
                for (int nt = 0; nt < 8; nt++) MMA4H(acc[mt][nt], ah[mt], bh[nt][0], bh[nt][1]);
        }

        scur = (scur == 2) ? 0 : scur + 1;
        spre = (spre == 2) ? 0 : spre + 1;
    }

#pragma unroll
    for (int mt = 0; mt < 4; mt++) {
        const int r0 = row0 + wm * 64 + mt * 16 + g;
#pragma unroll
        for (int nt = 0; nt < 8; nt++) {
            const int cb = col0 + wn * 64 + nt * 8 + 2 * cq;
            *(float2*)&C[(size_t)r0 * N + cb]       = make_float2(acc[mt][nt][0], acc[mt][nt][1]);
            *(float2*)&C[(size_t)(r0 + 8) * N + cb] = make_float2(acc[mt][nt][2], acc[mt][nt][3]);
        }
    }
}

// ---------------------------------------------------------------------------
// RoPE + scale(log2e) + fp16 outputs: q single, k hi+lo, v single.
// ---------------------------------------------------------------------------
__global__ void rope_split_kernel(const float* __restrict__ qkv,
                                  const int* __restrict__ pos,
                                  __half* __restrict__ q16,
                                  __half* __restrict__ k16h, __half* __restrict__ k16l,
                                  __half* __restrict__ v16h)
{
    const int t = blockIdx.x;
    const int tid = threadIdx.x;
    const float p = (float)pos[t];
    const float* base = qkv + (size_t)t * QKV_N;

#pragma unroll
    for (int it = 0; it < 8; it++) {
        const int item = it * 128 + tid;
        const int head = item >> 6, j = item & 63;
        const float invf = powf(10000.0f, -((float)j) * (1.0f / 64.0f));
        float s, c; sincosf(p * invf, &s, &c);
        const float x1 = base[head * HD + j];
        const float x2 = base[head * HD + j + 64];
        const size_t o = (size_t)t * (NH * HD) + head * HD + j;
        q16[o]      = __float2half_rn((x1 * c - x2 * s) * SCALEL2);
        q16[o + 64] = __float2half_rn((x2 * c + x1 * s) * SCALEL2);
    }
#pragma unroll
    for (int it = 0; it < 2; it++) {
        const int item = it * 128 + tid;
        const int head = item >> 6, j = item & 63;
        const float invf = powf(10000.0f, -((float)j) * (1.0f / 64.0f));
        float s, c; sincosf(p * invf, &s, &c);
        const float x1 = base[NH * HD + head * HD + j];
        const float x2 = base[NH * HD + head * HD + j + 64];
        const float y1 = x1 * c - x2 * s;
        const float y2 = x2 * c + x1 * s;
        const size_t o = (size_t)t * (NKV * HD) + head * HD + j;
        __half h1 = __float2half_rn(y1), h2 = __float2half_rn(y2);
        k16h[o] = h1;      k16l[o]      = __float2half_rn(y1 - __half2float(h1));
        k16h[o + 64] = h2; k16l[o + 64] = __float2half_rn(y2 - __half2float(h2));
    }
#pragma unroll
    for (int it = 0; it < 4; it++) {
        const int idx = it * 128 + tid;
        const size_t o = (size_t)t * (NKV * HD) + idx;
        v16h[o] = __float2half_rn(base[(NH + NKV) * HD + idx]);
    }
}

// ---------------------------------------------------------------------------
// Flash attention: S = Qh*(Kh+Kl), O += Ph*Vh (V single fp16).
// BQ=BK=64, 128 threads, 3 smem arrays = 52224B -> up to 4 CTAs/SM.
// ---------------------------------------------------------------------------
#define PITCH 136
#define PITCHB (PITCH * 2)
#define AT_SMEM (3 * 64 * PITCH * 2)   // 52224

__global__ __launch_bounds__(128) void attn_mma_kernel(
    const __half* __restrict__ q16,
    const __half* __restrict__ k16h, const __half* __restrict__ k16l,
    const __half* __restrict__ v16h,
    __half* __restrict__ ctxh)
{
    extern __shared__ __half sm16[];
    __half* Kh = sm16;
    __half* Kl = sm16 + 64 * PITCH;
    __half* Vh = sm16 + 2 * 64 * PITCH;

    const int tid  = threadIdx.x;
    const int lane = tid & 31;
    const int w    = tid >> 5;
    const int gr   = lane >> 2;
    const int tq   = lane & 3;
    const int qb   = (int)gridDim.x - 1 - (int)blockIdx.x;
    const int h    = blockIdx.y;
    const int kvh  = h >> 2;
    const int q0   = qb * 64;

    const int lm = lane >> 3;
    const int laneoff = (((lm & 1) << 3) + (lane & 7)) * PITCHB + ((lm >> 1) << 3) * 2;

    const uint32_t sKh = (uint32_t)__cvta_generic_to_shared(Kh);
    const uint32_t sKl = (uint32_t)__cvta_generic_to_shared(Kl);
    const uint32_t sVh = (uint32_t)__cvta_generic_to_shared(Vh);

    // ---- stage Q (single fp16) into Kh area, extract fragments ----
#pragma unroll
    for (int it = 0; it < 8; it++) {
        const int idx = it * 128 + tid;
        const int row = idx >> 4;
        const int cc  = (idx & 15) * 8;
        const size_t gs = (size_t)(q0 + row) * (NH * HD) + h * HD + cc;
        *(uint4*)&Kh[row * PITCH + cc] = *(const uint4*)&q16[gs];
    }
    __syncthreads();

    uint32_t qf[8][4];
#pragma unroll
    for (int ks = 0; ks < 8; ks++)
        LDSM_X4(qf[ks][0], qf[ks][1], qf[ks][2], qf[ks][3],
                sKh + (16 * w) * PITCHB + (16 * ks) * 2 + laneoff);

    float o[16][4];
#pragma unroll
    for (int i = 0; i < 16; i++)
#pragma unroll
        for (int e = 0; e < 4; e++) o[i][e] = 0.0f;
    float mrun0 = -1e30f, mrun1 = -1e30f, lrun0 = 0.0f, lrun1 = 0.0f;

    for (int kb = 0; kb <= qb; kb++) {
        const int k0 = kb * 64;
        __syncthreads();

#pragma unroll
        for (int it = 0; it < 8; it++) {
            const int idx = it * 128 + tid;
            const int row = idx >> 4;
            const int cc  = (idx & 15) * 8;
            const size_t gs = (size_t)(k0 + row) * (NKV * HD) + kvh * HD + cc;
            const int ss = row * PITCH + cc;
            *(uint4*)&Kh[ss] = *(const uint4*)&k16h[gs];
            *(uint4*)&Kl[ss] = *(const uint4*)&k16l[gs];
            *(uint4*)&Vh[ss] = *(const uint4*)&v16h[gs];
        }
        __syncthreads();

        // ---- S = Q @ K^T ----
        float s[8][4];
#pragma unroll
        for (int i = 0; i < 8; i++)
#pragma unroll
            for (int e = 0; e < 4; e++) s[i][e] = 0.0f;

#pragma unroll
        for (int nt2 = 0; nt2 < 4; nt2++) {
#pragma unroll
            for (int ks = 0; ks < 8; ks++) {
                const int toff = (16 * nt2) * PITCHB + (16 * ks) * 2 + laneoff;
                uint32_t kh0, kh1, kh2, kh3, kl0, kl1, kl2, kl3;
                LDSM_X4(kh0, kh1, kh2, kh3, sKh + toff);
                LDSM_X4(kl0, kl1, kl2, kl3, sKl + toff);
                MMA4H(s[2 * nt2],     qf[ks], kh0, kh2);
                MMA4H(s[2 * nt2],     qf[ks], kl0, kl2);
                MMA4H(s[2 * nt2 + 1], qf[ks], kh1, kh3);
                MMA4H(s[2 * nt2 + 1], qf[ks], kl1, kl3);
            }
        }

        // ---- causal mask (diagonal block only) ----
        if (kb == qb) {
            const int lr0 = 16 * w + gr;
#pragma unroll
            for (int nt = 0; nt < 8; nt++) {
                const int c0 = 8 * nt + 2 * tq;
                if (c0     > lr0)     s[nt][0] = -1e30f;
                if (c0 + 1 > lr0)     s[nt][1] = -1e30f;
                if (c0     > lr0 + 8) s[nt][2] = -1e30f;
                if (c0 + 1 > lr0 + 8) s[nt][3] = -1e30f;
            }
        }

        // ---- online softmax (exp2 domain) ----
        float m0l = -1e30f, m1l = -1e30f;
#pragma unroll
        for (int nt = 0; nt < 8; nt++) {
            m0l = fmaxf(m0l, fmaxf(s[nt][0], s[nt][1]));
            m1l = fmaxf(m1l, fmaxf(s[nt][2], s[nt][3]));
        }
        m0l = fmaxf(m0l, __shfl_xor_sync(0xffffffffu, m0l, 1));
        m0l = fmaxf(m0l, __shfl_xor_sync(0xffffffffu, m0l, 2));
        m1l = fmaxf(m1l, __shfl_xor_sync(0xffffffffu, m1l, 1));
        m1l = fmaxf(m1l, __shfl_xor_sync(0xffffffffu, m1l, 2));
        const float mn0 = fmaxf(mrun0, m0l);
        const float mn1 = fmaxf(mrun1, m1l);
        const float corr0 = exp2f(mrun0 - mn0);
        const float corr1 = exp2f(mrun1 - mn1);
        mrun0 = mn0; mrun1 = mn1;
        float sum0 = 0.0f, sum1 = 0.0f;
#pragma unroll
        for (int nt = 0; nt < 8; nt++) {
            s[nt][0] = exp2f(s[nt][0] - mn0);
            s[nt][1] = exp2f(s[nt][1] - mn0);
            s[nt][2] = exp2f(s[nt][2] - mn1);
            s[nt][3] = exp2f(s[nt][3] - mn1);
            sum0 += s[nt][0] + s[nt][1];
            sum1 += s[nt][2] + s[nt][3];
        }
        sum0 += __shfl_xor_sync(0xffffffffu, sum0, 1);
        sum0 += __shfl_xor_sync(0xffffffffu, sum0, 2);
        sum1 += __shfl_xor_sync(0xffffffffu, sum1, 1);
        sum1 += __shfl_xor_sync(0xffffffffu, sum1, 2);
        lrun0 = lrun0 * corr0 + sum0;
        lrun1 = lrun1 * corr1 + sum1;

#pragma unroll
        for (int nt = 0; nt < 16; nt++) {
            o[nt][0] *= corr0; o[nt][1] *= corr0;
            o[nt][2] *= corr1; o[nt][3] *= corr1;
        }

        // ---- O += P @ V (single V pass) ----
#pragma unroll
        for (int kvs = 0; kvs < 4; kvs++) {
            uint32_t ph[4];
            ph[0] = packh(s[2 * kvs][0], s[2 * kvs][1]);
            ph[1] = packh(s[2 * kvs][2], s[2 * kvs][3]);
            ph[2] = packh(s[2 * kvs + 1][0], s[2 * kvs + 1][1]);
            ph[3] = packh(s[2 * kvs + 1][2], s[2 * kvs + 1][3]);
#pragma unroll
            for (int dn2 = 0; dn2 < 8; dn2++) {
                const int toff = (16 * kvs) * PITCHB + (16 * dn2) * 2 + laneoff;
                uint32_t vh0, vh1, vh2, vh3;
                LDSM_X4_T(vh0, vh1, vh2, vh3, sVh + toff);
                MMA4H(o[2 * dn2],     ph, vh0, vh1);
                MMA4H(o[2 * dn2 + 1], ph, vh2, vh3);
            }
        }
    }

    // ---- epilogue: normalize, emit fp16 ctx ----
    const float inv0 = 1.0f / lrun0;
    const float inv1 = 1.0f / lrun1;
    const int row0 = q0 + 16 * w + gr;
    const int row1 = row0 + 8;
#pragma unroll
    for (int nt = 0; nt < 16; nt++) {
        const int col = h * HD + 8 * nt + 2 * tq;
        *(__half2*)&ctxh[(size_t)row0 * CTX_N + col] =
            __floats2half2_rn(o[nt][0] * inv0, o[nt][1] * inv0);
        *(__half2*)&ctxh[(size_t)row1 * CTX_N + col] =
            __floats2half2_rn(o[nt][2] * inv1, o[nt][3] * inv1);
    }
}

// ---------------------------------------------------------------------------
// Launch pipeline.
// ---------------------------------------------------------------------------
extern "C" void kernel_launch(void* const* d_in, const int* in_sizes, int n_in,
                              void* d_out, int out_size)
{
    const float* hidden = (const float*)d_in[0];
    const int*   pos    = (const int*)d_in[1];
    const float* Wqkv   = (const float*)d_in[2];
    const float* Wo     = (const float*)d_in[3];
    float* out = (float*)d_out;

    float* qkv_d;
    __half *hid_h, *ctx_h, *wqkvT_h, *wqkvT_l, *woT_h;
    __half *q16, *k16h, *k16l, *v16h;
    cudaGetSymbolAddress((void**)&qkv_d, g_qkv);
    cudaGetSymbolAddress((void**)&hid_h, g_hid_h);
    cudaGetSymbolAddress((void**)&ctx_h, g_ctx_h);
    cudaGetSymbolAddress((void**)&wqkvT_h, g_wqkvT_h);
    cudaGetSymbolAddress((void**)&wqkvT_l, g_wqkvT_l);
    cudaGetSymbolAddress((void**)&woT_h, g_woT_h);
    cudaGetSymbolAddress((void**)&q16, g_q16);
    cudaGetSymbolAddress((void**)&k16h, g_k16h);
    cudaGetSymbolAddress((void**)&k16l, g_k16l);
    cudaGetSymbolAddress((void**)&v16h, g_v16h);

    cudaFuncSetAttribute(gemm_f16x2_kernel, cudaFuncAttributeMaxDynamicSharedMemorySize,
                         GEMM_SMEM2);
    cudaFuncSetAttribute(gemm_f16x1_kernel, cudaFuncAttributeMaxDynamicSharedMemorySize,
                         GEMM_SMEM1);
    cudaFuncSetAttribute(attn_mma_kernel, cudaFuncAttributeMaxDynamicSharedMemorySize,
                         AT_SMEM);

    conv16_kernel<<<(T_SEQ * HID_DIM) / (256 * 4), 256>>>(hidden, hid_h);
    split_T16_kernel<<<dim3(QKV_N / 32, HID_DIM / 32), dim3(32, 8)>>>(Wqkv, wqkvT_h, wqkvT_l, HID_DIM, QKV_N);
    trans_T16_kernel<<<dim3(HID_DIM / 32, CTX_N / 32), dim3(32, 8)>>>(Wo, woT_h, CTX_N, HID_DIM);

    // 1) qkv = hidden @ Wqkv  (fp16x2)
    gemm_f16x2_kernel<<<dim3(QKV_N / 128, T_SEQ / 128), 128, GEMM_SMEM2>>>(
        hid_h, wqkvT_h, wqkvT_l, qkv_d, T_SEQ, QKV_N, HID_DIM);

    // 2) RoPE + scale(log2e) + fp16 split
    rope_split_kernel<<<T_SEQ, 128>>>(qkv_d, pos, q16, k16h, k16l, v16h);

    // 3) causal GQA flash attention (fp16, K hi+lo, V single)
    attn_mma_kernel<<<dim3(T_SEQ / 64, NH), 128, AT_SMEM>>>(
        q16, k16h, k16l, v16h, ctx_h);

    // 4) out = ctx @ Wo  (fp16 single-pass)
    gemm_f16x1_kernel<<<dim3(HID_DIM / 128, T_SEQ / 128), 128, GEMM_SMEM1>>>(
        ctx_h, woT_h, out, T_SEQ, HID_DIM, CTX_N);
}

// round 16
// speedup vs baseline: 1.5665x; 1.2642x over previous
#include <cuda_runtime.h>
#include <cuda_bf16.h>
#include <cuda_fp16.h>
#include <math.h>
#include <cstdint>
#include <cstddef>

#define T_SEQ 2048
#define HID_DIM 2048
#define NH 16
#define NKV 4
#define HD 128
#define QKV_N ((NH + 2 * NKV) * HD)   // 3072
#define CTX_N (NH * HD)               // 2048
// 1/sqrt(128) * log2(e)
#define SCALEL2 0.12753139578983588f

// ---------------- scratch (no cudaMalloc allowed) ----------------
__device__ float g_qkv[T_SEQ * QKV_N];
__device__ __half g_hid_h[T_SEQ * HID_DIM];
__device__ __half g_wqkvT_h[QKV_N * HID_DIM];
__device__ __half g_woT_h[HID_DIM * CTX_N];
__device__ __half g_ctx_h[T_SEQ * CTX_N];
__device__ __half g_q16[T_SEQ * NH * HD];
__device__ __half g_k16h[T_SEQ * NKV * HD];
__device__ __half g_k16l[T_SEQ * NKV * HD];
__device__ __half g_v16h[T_SEQ * NKV * HD];

// ---------------- tiny helpers ----------------
__device__ __forceinline__ uint32_t packh(float lo, float hi) {
    uint32_t r;
    asm("cvt.rn.f16x2.f32 %0, %1, %2;" : "=r"(r) : "f"(hi), "f"(lo));
    return r;
}

#define MMA4H(d, a, b0_, b1_)                                                 \
    asm volatile(                                                             \
        "mma.sync.aligned.m16n8k16.row.col.f32.f16.f16.f32 "                  \
        "{%0,%1,%2,%3}, {%4,%5,%6,%7}, {%8,%9}, {%0,%1,%2,%3};\n"             \
        : "+f"((d)[0]), "+f"((d)[1]), "+f"((d)[2]), "+f"((d)[3])              \
        : "r"((a)[0]), "r"((a)[1]), "r"((a)[2]), "r"((a)[3]),                 \
          "r"(b0_), "r"(b1_))

#define LDSM_X4(r0, r1, r2, r3, a)                                            \
    asm volatile("ldmatrix.sync.aligned.m8n8.x4.shared.b16 {%0,%1,%2,%3}, [%4];" \
                 : "=r"(r0), "=r"(r1), "=r"(r2), "=r"(r3) : "r"(a))

#define LDSM_X4_T(r0, r1, r2, r3, a)                                          \
    asm volatile("ldmatrix.sync.aligned.m8n8.x4.trans.shared.b16 {%0,%1,%2,%3}, [%4];" \
                 : "=r"(r0), "=r"(r1), "=r"(r2), "=r"(r3) : "r"(a))

#define CP16(dst, src)                                                        \
    asm volatile("cp.async.cg.shared.global [%0], [%1], 16;\n"                \
                 :: "r"(dst), "l"(src))
#define CP_COMMIT() asm volatile("cp.async.commit_group;\n" ::: "memory")
#define CP_WAIT1()  asm volatile("cp.async.wait_group 1;\n" ::: "memory")

// ---------------------------------------------------------------------------
// fp32 -> fp16 convert.
// ---------------------------------------------------------------------------
__global__ void conv16_kernel(const float* __restrict__ X, __half* __restrict__ Y)
{
    const size_t i = ((size_t)blockIdx.x * blockDim.x + threadIdx.x) * 4;
    float4 v = *(const float4*)&X[i];
    *(__half2*)&Y[i]     = __floats2half2_rn(v.x, v.y);
    *(__half2*)&Y[i + 2] = __floats2half2_rn(v.z, v.w);
}

// ---------------------------------------------------------------------------
// Transpose: W[Kd][N] fp32 -> Wt fp16 [N][Kd].
// ---------------------------------------------------------------------------
__global__ void trans_T16_kernel(const float* __restrict__ W,
                                 __half* __restrict__ hi, int Kd, int N)
{
    __shared__ float tile[32][33];
    const int n0 = blockIdx.x * 32;
    const int k0 = blockIdx.y * 32;
    const int tx = threadIdx.x, ty = threadIdx.y;
#pragma unroll
    for (int i = 0; i < 32; i += 8)
        tile[ty + i][tx] = W[(size_t)(k0 + ty + i) * N + n0 + tx];
    __syncthreads();
#pragma unroll
    for (int i = 0; i < 32; i += 8)
        hi[(size_t)(n0 + ty + i) * Kd + k0 + tx] = __float2half_rn(tile[tx][ty + i]);
}

// ---------------------------------------------------------------------------
// fp16 single-pass GEMM. 2-array stages, 3 slots, 3 CTAs/SM.
// Block tile 128x128, KC=32, 4 warps, warp tile 64x64, one sync per k-iter.
// ---------------------------------------------------------------------------
#define TCAB 8192
#define SLOTB1 (2 * TCAB)
#define GEMM_SMEM1 (3 * SLOTB1)       // 49152

__global__ __launch_bounds__(128, 3) void gemm_f16x1_kernel(
    const __half* __restrict__ Ah, const __half* __restrict__ Bh,
    float* __restrict__ C, int M, int N, int Kd)
{
    extern __shared__ __half gsm[];
    const uint32_t smem0 = (uint32_t)__cvta_generic_to_shared(gsm);

    const int tid  = threadIdx.x;
    const int lane = tid & 31;
    const int wid  = tid >> 5;
    const int g    = lane >> 2;
    const int cq   = lane & 3;
    const int wm   = wid & 1;
    const int wn   = wid >> 1;
    const int row0 = blockIdx.y * 128;
    const int col0 = blockIdx.x * 128;

    const int lm  = lane >> 3;
    const int row_local = ((lm & 1) << 3) + (lane & 7);
    const int chi = lm >> 1;
    const int xorv = (row_local >> 1) & 3;
    const int lo0 = row_local * 64 + (((0 | chi) ^ xorv) << 4);
    const int lo1 = row_local * 64 + (((2 | chi) ^ xorv) << 4);

    uint32_t dsw[4];
    int goff[4];
#pragma unroll
    for (int i = 0; i < 4; i++) {
        const int c = i * 128 + tid;
        const int r = c >> 2, cc = c & 3;
        dsw[i] = r * 64 + ((cc ^ ((r >> 1) & 3)) << 4);
        goff[i] = r * Kd + cc * 8;
    }

    const __half* pAh = Ah + (size_t)row0 * Kd;
    const __half* pBh = Bh + (size_t)col0 * Kd;

    const int nK = Kd >> 5;

    float acc[4][8][4];
#pragma unroll
    for (int i = 0; i < 4; i++)
#pragma unroll
        for (int j = 0; j < 8; j++)
#pragma unroll
            for (int e = 0; e < 4; e++) acc[i][j][e] = 0.0f;

#pragma unroll
    for (int pf = 0; pf < 2; pf++) {
        const int k0 = pf * 32;
        const uint32_t sb = smem0 + pf * SLOTB1;
#pragma unroll
        for (int i = 0; i < 4; i++) {
            CP16(sb + dsw[i],        pAh + goff[i] + k0);
            CP16(sb + TCAB + dsw[i], pBh + goff[i] + k0);
        }
        CP_COMMIT();
    }

    int scur = 0, spre = 2;
    for (int kt = 0; kt < nK; kt++) {
        CP_WAIT1();
        __syncthreads();

        if (kt + 2 < nK) {
            const int k0 = (kt + 2) * 32;
            const uint32_t db = smem0 + spre * SLOTB1;
#pragma unroll
            for (int i = 0; i < 4; i++) {
                CP16(db + dsw[i],        pAh + goff[i] + k0);
                CP16(db + TCAB + dsw[i], pBh + goff[i] + k0);
            }
        }
        CP_COMMIT();

        const uint32_t sb  = smem0 + scur * SLOTB1;
        const uint32_t sAh = sb;
        const uint32_t sBh = sb + TCAB;

#pragma unroll
        for (int ks2 = 0; ks2 < 2; ks2++) {
            const int lo = ks2 ? lo1 : lo0;
            uint32_t ah[4][4], bh[8][2];
#pragma unroll
            for (int mt = 0; mt < 4; mt++) {
                const int off = (wm * 64 + mt * 16) * 64 + lo;
                LDSM_X4(ah[mt][0], ah[mt][1], ah[mt][2], ah[mt][3], sAh + off);
            }
#pragma unroll
            for (int np = 0; np < 4; np++) {
                const int off = (wn * 64 + np * 16) * 64 + lo;
                uint32_t t0, t1, t2, t3;
                LDSM_X4(t0, t1, t2, t3, sBh + off);
                bh[2 * np][0] = t0; bh[2 * np + 1][0] = t1;
                bh[2 * np][1] = t2; bh[2 * np + 1][1] = t3;
            }
#pragma unroll
            for (int mt = 0; mt < 4; mt++)
#pragma unroll
                for (int nt = 0; nt < 8; nt++) MMA4H(acc[mt][nt], ah[mt], bh[nt][0], bh[nt][1]);
        }

        scur = (scur == 2) ? 0 : scur + 1;
        spre = (spre == 2) ? 0 : spre + 1;
    }

#pragma unroll
    for (int mt = 0; mt < 4; mt++) {
        const int r0 = row0 + wm * 64 + mt * 16 + g;
#pragma unroll
        for (int nt = 0; nt < 8; nt++) {
            const int cb = col0 + wn * 64 + nt * 8 + 2 * cq;
            *(float2*)&C[(size_t)r0 * N + cb]       = make_float2(acc[mt][nt][0], acc[mt][nt][1]);
            *(float2*)&C[(size_t)(r0 + 8) * N + cb] = make_float2(acc[mt][nt][2], acc[mt][nt][3]);
        }
    }
}

// ---------------------------------------------------------------------------
// RoPE + scale(log2e) + fp16 outputs: q single, k hi+lo, v single.
// ---------------------------------------------------------------------------
__global__ void rope_split_kernel(const float* __restrict__ qkv,
                                  const int* __restrict__ pos,
                                  __half* __restrict__ q16,
                                  __half* __restrict__ k16h, __half* __restrict__ k16l,
                                  __half* __restrict__ v16h)
{
    const int t = blockIdx.x;
    const int tid = threadIdx.x;
    const float p = (float)pos[t];
    const float* base = qkv + (size_t)t * QKV_N;

#pragma unroll
    for (int it = 0; it < 8; it++) {
        const int item = it * 128 + tid;
        const int head = item >> 6, j = item & 63;
        const float invf = powf(10000.0f, -((float)j) * (1.0f / 64.0f));
        float s, c; sincosf(p * invf, &s, &c);
        const float x1 = base[head * HD + j];
        const float x2 = base[head * HD + j + 64];
        const size_t o = (size_t)t * (NH * HD) + head * HD + j;
        q16[o]      = __float2half_rn((x1 * c - x2 * s) * SCALEL2);
        q16[o + 64] = __float2half_rn((x2 * c + x1 * s) * SCALEL2);
    }
#pragma unroll
    for (int it = 0; it < 2; it++) {
        const int item = it * 128 + tid;
        const int head = item >> 6, j = item & 63;
        const float invf = powf(10000.0f, -((float)j) * (1.0f / 64.0f));
        float s, c; sincosf(p * invf, &s, &c);
        const float x1 = base[NH * HD + head * HD + j];
        const float x2 = base[NH * HD + head * HD + j + 64];
        const float y1 = x1 * c - x2 * s;
        const float y2 = x2 * c + x1 * s;
        const size_t o = (size_t)t * (NKV * HD) + head * HD + j;
        __half h1 = __float2half_rn(y1), h2 = __float2half_rn(y2);
        k16h[o] = h1;      k16l[o]      = __float2half_rn(y1 - __half2float(h1));
        k16h[o + 64] = h2; k16l[o + 64] = __float2half_rn(y2 - __half2float(h2));
    }
#pragma unroll
    for (int it = 0; it < 4; it++) {
        const int idx = it * 128 + tid;
        const size_t o = (size_t)t * (NKV * HD) + idx;
        v16h[o] = __float2half_rn(base[(NH + NKV) * HD + idx]);
    }
}

// ---------------------------------------------------------------------------
// Flash attention: S = Qh*(Kh+Kl), O += Ph*Vh. BQ=BK=64, 128 threads,
// 3 smem arrays = 52224B; __launch_bounds__(128,3) -> 3 CTAs/SM.
// ---------------------------------------------------------------------------
#define PITCH 136
#define PITCHB (PITCH * 2)
#define AT_SMEM (3 * 64 * PITCH * 2)   // 52224

__global__ __launch_bounds__(128, 3) void attn_mma_kernel(
    const __half* __restrict__ q16,
    const __half* __restrict__ k16h, const __half* __restrict__ k16l,
    const __half* __restrict__ v16h,
    __half* __restrict__ ctxh)
{
    extern __shared__ __half sm16[];
    __half* Kh = sm16;
    __half* Kl = sm16 + 64 * PITCH;
    __half* Vh = sm16 + 2 * 64 * PITCH;

    const int tid  = threadIdx.x;
    const int lane = tid & 31;
    const int w    = tid >> 5;
    const int gr   = lane >> 2;
    const int tq   = lane & 3;
    const int qb   = (int)gridDim.x - 1 - (int)blockIdx.x;
    const int h    = blockIdx.y;
    const int kvh  = h >> 2;
    const int q0   = qb * 64;

    const int lm = lane >> 3;
    const int laneoff = (((lm & 1) << 3) + (lane & 7)) * PITCHB + ((lm >> 1) << 3) * 2;

    const uint32_t sKh = (uint32_t)__cvta_generic_to_shared(Kh);
    const uint32_t sKl = (uint32_t)__cvta_generic_to_shared(Kl);
    const uint32_t sVh = (uint32_t)__cvta_generic_to_shared(Vh);

    // ---- stage Q (single fp16) into Kh area, extract fragments ----
#pragma unroll
    for (int it = 0; it < 8; it++) {
        const int idx = it * 128 + tid;
        const int row = idx >> 4;
        const int cc  = (idx & 15) * 8;
        const size_t gs = (size_t)(q0 + row) * (NH * HD) + h * HD + cc;
        *(uint4*)&Kh[row * PITCH + cc] = *(const uint4*)&q16[gs];
    }
    __syncthreads();

    uint32_t qf[8][4];
#pragma unroll
    for (int ks = 0; ks < 8; ks++)
        LDSM_X4(qf[ks][0], qf[ks][1], qf[ks][2], qf[ks][3],
                sKh + (16 * w) * PITCHB + (16 * ks) * 2 + laneoff);

    float o[16][4];
#pragma unroll
    for (int i = 0; i < 16; i++)
#pragma unroll
        for (int e = 0; e < 4; e++) o[i][e] = 0.0f;
    float mrun0 = -1e30f, mrun1 = -1e30f, lrun0 = 0.0f, lrun1 = 0.0f;

    for (int kb = 0; kb <= qb; kb++) {
        const int k0 = kb * 64;
        __syncthreads();

#pragma unroll
        for (int it = 0; it < 8; it++) {
            const int idx = it * 128 + tid;
            const int row = idx >> 4;
            const int cc  = (idx & 15) * 8;
            const size_t gs = (size_t)(k0 + row) * (NKV * HD) + kvh * HD + cc;
            const int ss = row * PITCH + cc;
            *(uint4*)&Kh[ss] = *(const uint4*)&k16h[gs];
            *(uint4*)&Kl[ss] = *(const uint4*)&k16l[gs];
            *(uint4*)&Vh[ss] = *(const uint4*)&v16h[gs];
        }
        __syncthreads();

        // ---- S = Q @ K^T ----
        float s[8][4];
#pragma unroll
        for (int i = 0; i < 8; i++)
#pragma unroll
            for (int e = 0; e < 4; e++) s[i][e] = 0.0f;

#pragma unroll
        for (int nt2 = 0; nt2 < 4; nt2++) {
#pragma unroll
            for (int ks = 0; ks < 8; ks++) {
                const int toff = (16 * nt2) * PITCHB + (16 * ks) * 2 + laneoff;
                uint32_t kh0, kh1, kh2, kh3, kl0, kl1, kl2, kl3;
                LDSM_X4(kh0, kh1, kh2, kh3, sKh + toff);
                LDSM_X4(kl0, kl1, kl2, kl3, sKl + toff);
                MMA4H(s[2 * nt2],     qf[ks], kh0, kh2);
                MMA4H(s[2 * nt2],     qf[ks], kl0, kl2);
                MMA4H(s[2 * nt2 + 1], qf[ks], kh1, kh3);
                MMA4H(s[2 * nt2 + 1], qf[ks], kl1, kl3);
            }
        }

        // ---- causal mask (diagonal block only) ----
        if (kb == qb) {
            const int lr0 = 16 * w + gr;
#pragma unroll
            for (int nt = 0; nt < 8; nt++) {
                const int c0 = 8 * nt + 2 * tq;
                if (c0     > lr0)     s[nt][0] = -1e30f;
                if (c0 + 1 > lr0)     s[nt][1] = -1e30f;
                if (c0     > lr0 + 8) s[nt][2] = -1e30f;
                if (c0 + 1 > lr0 + 8) s[nt][3] = -1e30f;
            }
        }

        // ---- online softmax (exp2 domain) ----
        float m0l = -1e30f, m1l = -1e30f;
#pragma unroll
        for (int nt = 0; nt < 8; nt++) {
            m0l = fmaxf(m0l, fmaxf(s[nt][0], s[nt][1]));
            m1l = fmaxf(m1l, fmaxf(s[nt][2], s[nt][3]));
        }
        m0l = fmaxf(m0l, __shfl_xor_sync(0xffffffffu, m0l, 1));
        m0l = fmaxf(m0l, __shfl_xor_sync(0xffffffffu, m0l, 2));
        m1l = fmaxf(m1l, __shfl_xor_sync(0xffffffffu, m1l, 1));
        m1l = fmaxf(m1l, __shfl_xor_sync(0xffffffffu, m1l, 2));
        const float mn0 = fmaxf(mrun0, m0l);
        const float mn1 = fmaxf(mrun1, m1l);
        const float corr0 = exp2f(mrun0 - mn0);
        const float corr1 = exp2f(mrun1 - mn1);
        mrun0 = mn0; mrun1 = mn1;
        float sum0 = 0.0f, sum1 = 0.0f;
#pragma unroll
        for (int nt = 0; nt < 8; nt++) {
            s[nt][0] = exp2f(s[nt][0] - mn0);
            s[nt][1] = exp2f(s[nt][1] - mn0);
            s[nt][2] = exp2f(s[nt][2] - mn1);
            s[nt][3] = exp2f(s[nt][3] - mn1);
            sum0 += s[nt][0] + s[nt][1];
            sum1 += s[nt][2] + s[nt][3];
        }
        sum0 += __shfl_xor_sync(0xffffffffu, sum0, 1);
        sum0 += __shfl_xor_sync(0xffffffffu, sum0, 2);
        sum1 += __shfl_xor_sync(0xffffffffu, sum1, 1);
        sum1 += __shfl_xor_sync(0xffffffffu, sum1, 2);
        lrun0 = lrun0 * corr0 + sum0;
        lrun1 = lrun1 * corr1 + sum1;

#pragma unroll
        for (int nt = 0; nt < 16; nt++) {
            o[nt][0] *= corr0; o[nt][1] *= corr0;
            o[nt][2] *= corr1; o[nt][3] *= corr1;
        }

        // ---- O += P @ V ----
#pragma unroll
        for (int kvs = 0; kvs < 4; kvs++) {
            uint32_t ph[4];
            ph[0] = packh(s[2 * kvs][0], s[2 * kvs][1]);
            ph[1] = packh(s[2 * kvs][2], s[2 * kvs][3]);
            ph[2] = packh(s[2 * kvs + 1][0], s[2 * kvs + 1][1]);
            ph[3] = packh(s[2 * kvs + 1][2], s[2 * kvs + 1][3]);
#pragma unroll
            for (int dn2 = 0; dn2 < 8; dn2++) {
                const int toff = (16 * kvs) * PITCHB + (16 * dn2) * 2 + laneoff;
                uint32_t vh0, vh1, vh2, vh3;
                LDSM_X4_T(vh0, vh1, vh2, vh3, sVh + toff);
                MMA4H(o[2 * dn2],     ph, vh0, vh1);
                MMA4H(o[2 * dn2 + 1], ph, vh2, vh3);
            }
        }
    }

    // ---- epilogue: normalize, emit fp16 ctx ----
    const float inv0 = 1.0f / lrun0;
    const float inv1 = 1.0f / lrun1;
    const int row0 = q0 + 16 * w + gr;
    const int row1 = row0 + 8;
#pragma unroll
    for (int nt = 0; nt < 16; nt++) {
        const int col = h * HD + 8 * nt + 2 * tq;
        *(__half2*)&ctxh[(size_t)row0 * CTX_N + col] =
            __floats2half2_rn(o[nt][0] * inv0, o[nt][1] * inv0);
        *(__half2*)&ctxh[(size_t)row1 * CTX_N + col] =
            __floats2half2_rn(o[nt][2] * inv1, o[nt][3] * inv1);
    }
}

// ---------------------------------------------------------------------------
// Launch pipeline.
// ---------------------------------------------------------------------------
extern "C" void kernel_launch(void* const* d_in, const int* in_sizes, int n_in,
                              void* d_out, int out_size)
{
    const float* hidden = (const float*)d_in[0];
    const int*   pos    = (const int*)d_in[1];
    const float* Wqkv   = (const float*)d_in[2];
    const float* Wo     = (const float*)d_in[3];
    float* out = (float*)d_out;

    float* qkv_d;
    __half *hid_h, *ctx_h, *wqkvT_h, *woT_h;
    __half *q16, *k16h, *k16l, *v16h;
    cudaGetSymbolAddress((void**)&qkv_d, g_qkv);
    cudaGetSymbolAddress((void**)&hid_h, g_hid_h);
    cudaGetSymbolAddress((void**)&ctx_h, g_ctx_h);
    cudaGetSymbolAddress((void**)&wqkvT_h, g_wqkvT_h);
    cudaGetSymbolAddress((void**)&woT_h, g_woT_h);
    cudaGetSymbolAddress((void**)&q16, g_q16);
    cudaGetSymbolAddress((void**)&k16h, g_k16h);
    cudaGetSymbolAddress((void**)&k16l, g_k16l);
    cudaGetSymbolAddress((void**)&v16h, g_v16h);

    cudaFuncSetAttribute(gemm_f16x1_kernel, cudaFuncAttributeMaxDynamicSharedMemorySize,
                         GEMM_SMEM1);
    cudaFuncSetAttribute(attn_mma_kernel, cudaFuncAttributeMaxDynamicSharedMemorySize,
                         AT_SMEM);

    conv16_kernel<<<(T_SEQ * HID_DIM) / (256 * 4), 256>>>(hidden, hid_h);
    trans_T16_kernel<<<dim3(QKV_N / 32, HID_DIM / 32), dim3(32, 8)>>>(Wqkv, wqkvT_h, HID_DIM, QKV_N);
    trans_T16_kernel<<<dim3(HID_DIM / 32, CTX_N / 32), dim3(32, 8)>>>(Wo, woT_h, CTX_N, HID_DIM);

    // 1) qkv = hidden @ Wqkv  (fp16 single-pass)
    gemm_f16x1_kernel<<<dim3(QKV_N / 128, T_SEQ / 128), 128, GEMM_SMEM1>>>(
        hid_h, wqkvT_h, qkv_d, T_SEQ, QKV_N, HID_DIM);

    // 2) RoPE + scale(log2e) + fp16 split
    rope_split_kernel<<<T_SEQ, 128>>>(qkv_d, pos, q16, k16h, k16l, v16h);

    // 3) causal GQA flash attention (fp16, K hi+lo, V single)
    attn_mma_kernel<<<dim3(T_SEQ / 64, NH), 128, AT_SMEM>>>(
        q16, k16h, k16l, v16h, ctx_h);

    // 4) out = ctx @ Wo  (fp16 single-pass)
    gemm_f16x1_kernel<<<dim3(HID_DIM / 128, T_SEQ / 128), 128, GEMM_SMEM1>>>(
        ctx_h, woT_h, out, T_SEQ, HID_DIM, CTX_N);
}

// round 17
// speedup vs baseline: 1.7780x; 1.1350x over previous
#include <cuda_runtime.h>
#include <cuda_bf16.h>
#include <cuda_fp16.h>
#include <math.h>
#include <cstdint>
#include <cstddef>

#define T_SEQ 2048
#define HID_DIM 2048
#define NH 16
#define NKV 4
#define HD 128
#define QKV_N ((NH + 2 * NKV) * HD)   // 3072
#define CTX_N (NH * HD)               // 2048
// 1/sqrt(128) * log2(e)
#define SCALEL2 0.12753139578983588f

// ---------------- scratch (no cudaMalloc allowed) ----------------
__device__ float g_qkv[T_SEQ * QKV_N];
__device__ __half g_hid_h[T_SEQ * HID_DIM];
__device__ __half g_wqkvT_h[QKV_N * HID_DIM];
__device__ __half g_woT_h[HID_DIM * CTX_N];
__device__ __half g_ctx_h[T_SEQ * CTX_N];
__device__ __half g_q16[T_SEQ * NH * HD];
__device__ __half g_k16h[T_SEQ * NKV * HD];
__device__ __half g_v16h[T_SEQ * NKV * HD];

// ---------------- tiny helpers ----------------
__device__ __forceinline__ uint32_t packh(float lo, float hi) {
    uint32_t r;
    asm("cvt.rn.f16x2.f32 %0, %1, %2;" : "=r"(r) : "f"(hi), "f"(lo));
    return r;
}

#define MMA4H(d, a, b0_, b1_)                                                 \
    asm volatile(                                                             \
        "mma.sync.aligned.m16n8k16.row.col.f32.f16.f16.f32 "                  \
        "{%0,%1,%2,%3}, {%4,%5,%6,%7}, {%8,%9}, {%0,%1,%2,%3};\n"             \
        : "+f"((d)[0]), "+f"((d)[1]), "+f"((d)[2]), "+f"((d)[3])              \
        : "r"((a)[0]), "r"((a)[1]), "r"((a)[2]), "r"((a)[3]),                 \
          "r"(b0_), "r"(b1_))

#define LDSM_X4(r0, r1, r2, r3, a)                                            \
    asm volatile("ldmatrix.sync.aligned.m8n8.x4.shared.b16 {%0,%1,%2,%3}, [%4];" \
                 : "=r"(r0), "=r"(r1), "=r"(r2), "=r"(r3) : "r"(a))

#define LDSM_X4_T(r0, r1, r2, r3, a)                                          \
    asm volatile("ldmatrix.sync.aligned.m8n8.x4.trans.shared.b16 {%0,%1,%2,%3}, [%4];" \
                 : "=r"(r0), "=r"(r1), "=r"(r2), "=r"(r3) : "r"(a))

#define CP16(dst, src)                                                        \
    asm volatile("cp.async.cg.shared.global [%0], [%1], 16;\n"                \
                 :: "r"(dst), "l"(src))
#define CP_COMMIT() asm volatile("cp.async.commit_group;\n" ::: "memory")
#define CP_WAIT1()  asm volatile("cp.async.wait_group 1;\n" ::: "memory")

// ---------------------------------------------------------------------------
// fp32 -> fp16 convert.
// ---------------------------------------------------------------------------
__global__ void conv16_kernel(const float* __restrict__ X, __half* __restrict__ Y)
{
    const size_t i = ((size_t)blockIdx.x * blockDim.x + threadIdx.x) * 4;
    float4 v = *(const float4*)&X[i];
    *(__half2*)&Y[i]     = __floats2half2_rn(v.x, v.y);
    *(__half2*)&Y[i + 2] = __floats2half2_rn(v.z, v.w);
}

// ---------------------------------------------------------------------------
// Transpose: W[Kd][N] fp32 -> Wt fp16 [N][Kd].
// ---------------------------------------------------------------------------
__global__ void trans_T16_kernel(const float* __restrict__ W,
                                 __half* __restrict__ hi, int Kd, int N)
{
    __shared__ float tile[32][33];
    const int n0 = blockIdx.x * 32;
    const int k0 = blockIdx.y * 32;
    const int tx = threadIdx.x, ty = threadIdx.y;
#pragma unroll
    for (int i = 0; i < 32; i += 8)
        tile[ty + i][tx] = W[(size_t)(k0 + ty + i) * N + n0 + tx];
    __syncthreads();
#pragma unroll
    for (int i = 0; i < 32; i += 8)
        hi[(size_t)(n0 + ty + i) * Kd + k0 + tx] = __float2half_rn(tile[tx][ty + i]);
}

// ---------------------------------------------------------------------------
// fp16 single-pass GEMM (unchanged from round 16).
// ---------------------------------------------------------------------------
#define TCAB 8192
#define SLOTB1 (2 * TCAB)
#define GEMM_SMEM1 (3 * SLOTB1)       // 49152

__global__ __launch_bounds__(128, 3) void gemm_f16x1_kernel(
    const __half* __restrict__ Ah, const __half* __restrict__ Bh,
    float* __restrict__ C, int M, int N, int Kd)
{
    extern __shared__ __half gsm[];
    const uint32_t smem0 = (uint32_t)__cvta_generic_to_shared(gsm);

    const int tid  = threadIdx.x;
    const int lane = tid & 31;
    const int wid  = tid >> 5;
    const int g    = lane >> 2;
    const int cq   = lane & 3;
    const int wm   = wid & 1;
    const int wn   = wid >> 1;
    const int row0 = blockIdx.y * 128;
    const int col0 = blockIdx.x * 128;

    const int lm  = lane >> 3;
    const int row_local = ((lm & 1) << 3) + (lane & 7);
    const int chi = lm >> 1;
    const int xorv = (row_local >> 1) & 3;
    const int lo0 = row_local * 64 + (((0 | chi) ^ xorv) << 4);
    const int lo1 = row_local * 64 + (((2 | chi) ^ xorv) << 4);

    uint32_t dsw[4];
    int goff[4];
#pragma unroll
    for (int i = 0; i < 4; i++) {
        const int c = i * 128 + tid;
        const int r = c >> 2, cc = c & 3;
        dsw[i] = r * 64 + ((cc ^ ((r >> 1) & 3)) << 4);
        goff[i] = r * Kd + cc * 8;
    }

    const __half* pAh = Ah + (size_t)row0 * Kd;
    const __half* pBh = Bh + (size_t)col0 * Kd;

    const int nK = Kd >> 5;

    float acc[4][8][4];
#pragma unroll
    for (int i = 0; i < 4; i++)
#pragma unroll
        for (int j = 0; j < 8; j++)
#pragma unroll
            for (int e = 0; e < 4; e++) acc[i][j][e] = 0.0f;

#pragma unroll
    for (int pf = 0; pf < 2; pf++) {
        const int k0 = pf * 32;
        const uint32_t sb = smem0 + pf * SLOTB1;
#pragma unroll
        for (int i = 0; i < 4; i++) {
            CP16(sb + dsw[i],        pAh + goff[i] + k0);
            CP16(sb + TCAB + dsw[i], pBh + goff[i] + k0);
        }
        CP_COMMIT();
    }

    int scur = 0, spre = 2;
    for (int kt = 0; kt < nK; kt++) {
        CP_WAIT1();
        __syncthreads();

        if (kt + 2 < nK) {
            const int k0 = (kt + 2) * 32;
            const uint32_t db = smem0 + spre * SLOTB1;
#pragma unroll
            for (int i = 0; i < 4; i++) {
                CP16(db + dsw[i],        pAh + goff[i] + k0);
                CP16(db + TCAB + dsw[i], pBh + goff[i] + k0);
            }
        }
        CP_COMMIT();

        const uint32_t sb  = smem0 + scur * SLOTB1;
        const uint32_t sAh = sb;
        const uint32_t sBh = sb + TCAB;

#pragma unroll
        for (int ks2 = 0; ks2 < 2; ks2++) {
            const int lo = ks2 ? lo1 : lo0;
            uint32_t ah[4][4], bh[8][2];
#pragma unroll
            for (int mt = 0; mt < 4; mt++) {
                const int off = (wm * 64 + mt * 16) * 64 + lo;
                LDSM_X4(ah[mt][0], ah[mt][1], ah[mt][2], ah[mt][3], sAh + off);
            }
#pragma unroll
            for (int np = 0; np < 4; np++) {
                const int off = (wn * 64 + np * 16) * 64 + lo;
                uint32_t t0, t1, t2, t3;
                LDSM_X4(t0, t1, t2, t3, sBh + off);
                bh[2 * np][0] = t0; bh[2 * np + 1][0] = t1;
                bh[2 * np][1] = t2; bh[2 * np + 1][1] = t3;
            }
#pragma unroll
            for (int mt = 0; mt < 4; mt++)
#pragma unroll
                for (int nt = 0; nt < 8; nt++) MMA4H(acc[mt][nt], ah[mt], bh[nt][0], bh[nt][1]);
        }

        scur = (scur == 2) ? 0 : scur + 1;
        spre = (spre == 2) ? 0 : spre + 1;
    }

#pragma unroll
    for (int mt = 0; mt < 4; mt++) {
        const int r0 = row0 + wm * 64 + mt * 16 + g;
#pragma unroll
        for (int nt = 0; nt < 8; nt++) {
            const int cb = col0 + wn * 64 + nt * 8 + 2 * cq;
            *(float2*)&C[(size_t)r0 * N + cb]       = make_float2(acc[mt][nt][0], acc[mt][nt][1]);
            *(float2*)&C[(size_t)(r0 + 8) * N + cb] = make_float2(acc[mt][nt][2], acc[mt][nt][3]);
        }
    }
}

// ---------------------------------------------------------------------------
// RoPE + scale(log2e) + fp16 outputs: q, k, v all single fp16.
// ---------------------------------------------------------------------------
__global__ void rope_split_kernel(const float* __restrict__ qkv,
                                  const int* __restrict__ pos,
                                  __half* __restrict__ q16,
                                  __half* __restrict__ k16h,
                                  __half* __restrict__ v16h)
{
    const int t = blockIdx.x;
    const int tid = threadIdx.x;
    const float p = (float)pos[t];
    const float* base = qkv + (size_t)t * QKV_N;

#pragma unroll
    for (int it = 0; it < 8; it++) {
        const int item = it * 128 + tid;
        const int head = item >> 6, j = item & 63;
        const float invf = powf(10000.0f, -((float)j) * (1.0f / 64.0f));
        float s, c; sincosf(p * invf, &s, &c);
        const float x1 = base[head * HD + j];
        const float x2 = base[head * HD + j + 64];
        const size_t o = (size_t)t * (NH * HD) + head * HD + j;
        q16[o]      = __float2half_rn((x1 * c - x2 * s) * SCALEL2);
        q16[o + 64] = __float2half_rn((x2 * c + x1 * s) * SCALEL2);
    }
#pragma unroll
    for (int it = 0; it < 2; it++) {
        const int item = it * 128 + tid;
        const int head = item >> 6, j = item & 63;
        const float invf = powf(10000.0f, -((float)j) * (1.0f / 64.0f));
        float s, c; sincosf(p * invf, &s, &c);
        const float x1 = base[NH * HD + head * HD + j];
        const float x2 = base[NH * HD + head * HD + j + 64];
        const size_t o = (size_t)t * (NKV * HD) + head * HD + j;
        k16h[o]      = __float2half_rn(x1 * c - x2 * s);
        k16h[o + 64] = __float2half_rn(x2 * c + x1 * s);
    }
#pragma unroll
    for (int it = 0; it < 4; it++) {
        const int idx = it * 128 + tid;
        const size_t o = (size_t)t * (NKV * HD) + idx;
        v16h[o] = __float2half_rn(base[(NH + NKV) * HD + idx]);
    }
}

// ---------------------------------------------------------------------------
// Flash attention, all-fp16: S = Qh*Kh, O += Ph*Vh. BQ=BK=64, 128 threads,
// 2 smem arrays = 34816B, __launch_bounds__(128,3).
// ---------------------------------------------------------------------------
#define PITCH 136
#define PITCHB (PITCH * 2)
#define AT_SMEM (2 * 64 * PITCH * 2)   // 34816

__global__ __launch_bounds__(128, 3) void attn_mma_kernel(
    const __half* __restrict__ q16,
    const __half* __restrict__ k16h,
    const __half* __restrict__ v16h,
    __half* __restrict__ ctxh)
{
    extern __shared__ __half sm16[];
    __half* Kh = sm16;
    __half* Vh = sm16 + 64 * PITCH;

    const int tid  = threadIdx.x;
    const int lane = tid & 31;
    const int w    = tid >> 5;
    const int gr   = lane >> 2;
    const int tq   = lane & 3;
    const int qb   = (int)gridDim.x - 1 - (int)blockIdx.x;
    const int h    = blockIdx.y;
    const int kvh  = h >> 2;
    const int q0   = qb * 64;

    const int lm = lane >> 3;
    const int laneoff = (((lm & 1) << 3) + (lane & 7)) * PITCHB + ((lm >> 1) << 3) * 2;

    const uint32_t sKh = (uint32_t)__cvta_generic_to_shared(Kh);
    const uint32_t sVh = (uint32_t)__cvta_generic_to_shared(Vh);

    // ---- stage Q into Kh area, extract fragments ----
#pragma unroll
    for (int it = 0; it < 8; it++) {
        const int idx = it * 128 + tid;
        const int row = idx >> 4;
        const int cc  = (idx & 15) * 8;
        const size_t gs = (size_t)(q0 + row) * (NH * HD) + h * HD + cc;
        *(uint4*)&Kh[row * PITCH + cc] = *(const uint4*)&q16[gs];
    }
    __syncthreads();

    uint32_t qf[8][4];
#pragma unroll
    for (int ks = 0; ks < 8; ks++)
        LDSM_X4(qf[ks][0], qf[ks][1], qf[ks][2], qf[ks][3],
                sKh + (16 * w) * PITCHB + (16 * ks) * 2 + laneoff);

    float o[16][4];
#pragma unroll
    for (int i = 0; i < 16; i++)
#pragma unroll
        for (int e = 0; e < 4; e++) o[i][e] = 0.0f;
    float mrun0 = -1e30f, mrun1 = -1e30f, lrun0 = 0.0f, lrun1 = 0.0f;

    for (int kb = 0; kb <= qb; kb++) {
        const int k0 = kb * 64;
        __syncthreads();

#pragma unroll
        for (int it = 0; it < 8; it++) {
            const int idx = it * 128 + tid;
            const int row = idx >> 4;
            const int cc  = (idx & 15) * 8;
            const size_t gs = (size_t)(k0 + row) * (NKV * HD) + kvh * HD + cc;
            const int ss = row * PITCH + cc;
            *(uint4*)&Kh[ss] = *(const uint4*)&k16h[gs];
            *(uint4*)&Vh[ss] = *(const uint4*)&v16h[gs];
        }
        __syncthreads();

        // ---- S = Q @ K^T (single fp16 pass) ----
        float s[8][4];
#pragma unroll
        for (int i = 0; i < 8; i++)
#pragma unroll
            for (int e = 0; e < 4; e++) s[i][e] = 0.0f;

#pragma unroll
        for (int nt2 = 0; nt2 < 4; nt2++) {
#pragma unroll
            for (int ks = 0; ks < 8; ks++) {
                const int toff = (16 * nt2) * PITCHB + (16 * ks) * 2 + laneoff;
                uint32_t kh0, kh1, kh2, kh3;
                LDSM_X4(kh0, kh1, kh2, kh3, sKh + toff);
                MMA4H(s[2 * nt2],     qf[ks], kh0, kh2);
                MMA4H(s[2 * nt2 + 1], qf[ks], kh1, kh3);
            }
        }

        // ---- causal mask (diagonal block only) ----
        if (kb == qb) {
            const int lr0 = 16 * w + gr;
#pragma unroll
            for (int nt = 0; nt < 8; nt++) {
                const int c0 = 8 * nt + 2 * tq;
                if (c0     > lr0)     s[nt][0] = -1e30f;
                if (c0 + 1 > lr0)     s[nt][1] = -1e30f;
                if (c0     > lr0 + 8) s[nt][2] = -1e30f;
                if (c0 + 1 > lr0 + 8) s[nt][3] = -1e30f;
            }
        }

        // ---- online softmax (exp2 domain) ----
        float m0l = -1e30f, m1l = -1e30f;
#pragma unroll
        for (int nt = 0; nt < 8; nt++) {
            m0l = fmaxf(m0l, fmaxf(s[nt][0], s[nt][1]));
            m1l = fmaxf(m1l, fmaxf(s[nt][2], s[nt][3]));
        }
        m0l = fmaxf(m0l, __shfl_xor_sync(0xffffffffu, m0l, 1));
        m0l = fmaxf(m0l, __shfl_xor_sync(0xffffffffu, m0l, 2));
        m1l = fmaxf(m1l, __shfl_xor_sync(0xffffffffu, m1l, 1));
        m1l = fmaxf(m1l, __shfl_xor_sync(0xffffffffu, m1l, 2));
        const float mn0 = fmaxf(mrun0, m0l);
        const float mn1 = fmaxf(mrun1, m1l);
        const float corr0 = exp2f(mrun0 - mn0);
        const float corr1 = exp2f(mrun1 - mn1);
        mrun0 = mn0; mrun1 = mn1;
        float sum0 = 0.0f, sum1 = 0.0f;
#pragma unroll
        for (int nt = 0; nt < 8; nt++) {
            s[nt][0] = exp2f(s[nt][0] - mn0);
            s[nt][1] = exp2f(s[nt][1] - mn0);
            s[nt][2] = exp2f(s[nt][2] - mn1);
            s[nt][3] = exp2f(s[nt][3] - mn1);
            sum0 += s[nt][0] + s[nt][1];
            sum1 += s[nt][2] + s[nt][3];
        }
        sum0 += __shfl_xor_sync(0xffffffffu, sum0, 1);
        sum0 += __shfl_xor_sync(0xffffffffu, sum0, 2);
        sum1 += __shfl_xor_sync(0xffffffffu, sum1, 1);
        sum1 += __shfl_xor_sync(0xffffffffu, sum1, 2);
        lrun0 = lrun0 * corr0 + sum0;
        lrun1 = lrun1 * corr1 + sum1;

#pragma unroll
        for (int nt = 0; nt < 16; nt++) {
            o[nt][0] *= corr0; o[nt][1] *= corr0;
            o[nt][2] *= corr1; o[nt][3] *= corr1;
        }

        // ---- O += P @ V ----
#pragma unroll
        for (int kvs = 0; kvs < 4; kvs++) {
            uint32_t ph[4];
            ph[0] = packh(s[2 * kvs][0], s[2 * kvs][1]);
            ph[1] = packh(s[2 * kvs][2], s[2 * kvs][3]);
            ph[2] = packh(s[2 * kvs + 1][0], s[2 * kvs + 1][1]);
            ph[3] = packh(s[2 * kvs + 1][2], s[2 * kvs + 1][3]);
#pragma unroll
            for (int dn2 = 0; dn2 < 8; dn2++) {
                const int toff = (16 * kvs) * PITCHB + (16 * dn2) * 2 + laneoff;
                uint32_t vh0, vh1, vh2, vh3;
                LDSM_X4_T(vh0, vh1, vh2, vh3, sVh + toff);
                MMA4H(o[2 * dn2],     ph, vh0, vh1);
                MMA4H(o[2 * dn2 + 1], ph, vh2, vh3);
            }
        }
    }

    // ---- epilogue: normalize, emit fp16 ctx ----
    const float inv0 = 1.0f / lrun0;
    const float inv1 = 1.0f / lrun1;
    const int row0 = q0 + 16 * w + gr;
    const int row1 = row0 + 8;
#pragma unroll
    for (int nt = 0; nt < 16; nt++) {
        const int col = h * HD + 8 * nt + 2 * tq;
        *(__half2*)&ctxh[(size_t)row0 * CTX_N + col] =
            __floats2half2_rn(o[nt][0] * inv0, o[nt][1] * inv0);
        *(__half2*)&ctxh[(size_t)row1 * CTX_N + col] =
            __floats2half2_rn(o[nt][2] * inv1, o[nt][3] * inv1);
    }
}

// ---------------------------------------------------------------------------
// Launch pipeline.
// ---------------------------------------------------------------------------
extern "C" void kernel_launch(void* const* d_in, const int* in_sizes, int n_in,
                              void* d_out, int out_size)
{
    const float* hidden = (const float*)d_in[0];
    const int*   pos    = (const int*)d_in[1];
    const float* Wqkv   = (const float*)d_in[2];
    const float* Wo     = (const float*)d_in[3];
    float* out = (float*)d_out;

    float* qkv_d;
    __half *hid_h, *ctx_h, *wqkvT_h, *woT_h;
    __half *q16, *k16h, *v16h;
    cudaGetSymbolAddress((void**)&qkv_d, g_qkv);
    cudaGetSymbolAddress((void**)&hid_h, g_hid_h);
    cudaGetSymbolAddress((void**)&ctx_h, g_ctx_h);
    cudaGetSymbolAddress((void**)&wqkvT_h, g_wqkvT_h);
    cudaGetSymbolAddress((void**)&woT_h, g_woT_h);
    cudaGetSymbolAddress((void**)&q16, g_q16);
    cudaGetSymbolAddress((void**)&k16h, g_k16h);
    cudaGetSymbolAddress((void**)&v16h, g_v16h);

    cudaFuncSetAttribute(gemm_f16x1_kernel, cudaFuncAttributeMaxDynamicSharedMemorySize,
                         GEMM_SMEM1);
    cudaFuncSetAttribute(attn_mma_kernel, cudaFuncAttributeMaxDynamicSharedMemorySize,
                         AT_SMEM);

    conv16_kernel<<<(T_SEQ * HID_DIM) / (256 * 4), 256>>>(hidden, hid_h);
    trans_T16_kernel<<<dim3(QKV_N / 32, HID_DIM / 32), dim3(32, 8)>>>(Wqkv, wqkvT_h, HID_DIM, QKV_N);
    trans_T16_kernel<<<dim3(HID_DIM / 32, CTX_N / 32), dim3(32, 8)>>>(Wo, woT_h, CTX_N, HID_DIM);

    // 1) qkv = hidden @ Wqkv  (fp16 single-pass)
    gemm_f16x1_kernel<<<dim3(QKV_N / 128, T_SEQ / 128), 128, GEMM_SMEM1>>>(
        hid_h, wqkvT_h, qkv_d, T_SEQ, QKV_N, HID_DIM);

    // 2) RoPE + scale(log2e) + fp16 outputs
    rope_split_kernel<<<T_SEQ, 128>>>(qkv_d, pos, q16, k16h, v16h);

    // 3) causal GQA flash attention (all fp16)
    attn_mma_kernel<<<dim3(T_SEQ / 64, NH), 128, AT_SMEM>>>(
        q16, k16h, v16h, ctx_h);

    // 4) out = ctx @ Wo  (fp16 single-pass)
    gemm_f16x1_kernel<<<dim3(HID_DIM / 128, T_SEQ / 128), 128, GEMM_SMEM1>>>(
        ctx_h, woT_h, out, T_SEQ, HID_DIM, CTX_N);
}